// round 1
// baseline (speedup 1.0000x reference)
#include <cuda_runtime.h>
#include <math.h>

#define BB 4
#define NN 32
#define LL 256
#define HH 64
#define NI 31
#define PP 496
#define NEGV (-1e9f)

// ---------------- scratch (static __device__, no runtime allocs) ----------------
__device__ float g_pool[BB*NN*LL*HH];   // 8 MB
__device__ float g_u[BB*NN*LL*HH];      // 8 MB  pool @ Ws1[:H]
__device__ float g_v[BB*NN*LL*HH];      // 8 MB  pool @ Ws1[H:]
__device__ float g_means[BB*NN*HH];
__device__ float g_scores[BB*PP];       // cached raw pair scores
__device__ unsigned g_lsets[BB*NN];
__device__ int g_active[BB*NN];
__device__ unsigned g_clades[BB*NI];
__device__ int g_si[BB], g_sj[BB];
__device__ float g_loss[BB];

__device__ __forceinline__ void pdecode(int p, int& i, int& j) {
    int ii = 0;
    while (p >= NN - 1 - ii) { p -= NN - 1 - ii; ii++; }
    i = ii; j = ii + 1 + p;
}
__device__ __forceinline__ int pindex(int i, int j) {
    return i * (2 * NN - i - 1) / 2 + (j - i - 1);
}

// ---------------- init: embeds, u/v, means ----------------
// grid (NN, BB), 256 threads
__global__ void k_init_embed(const float* __restrict__ leaf, const float* __restrict__ We,
                             const float* __restrict__ be, const float* __restrict__ Ws1) {
    int n = blockIdx.x, b = blockIdx.y;
    int t = threadIdx.x, l4 = t >> 6, h = t & 63;
    __shared__ float sw1[128 * 64];
    __shared__ float se[4][64];
    __shared__ float sred[4][64];
    for (int idx = t; idx < 128 * 64; idx += 256) sw1[idx] = Ws1[idx];
    __syncthreads();
    float msum = 0.f;
    size_t base = ((size_t)(b * NN + n) * LL) * HH;
    for (int l0 = 0; l0 < LL; l0 += 4) {
        int l = l0 + l4;
        const float* lp = leaf + (((size_t)(b * NN + n) * LL + l) * 4);
        float a = be[h];
#pragma unroll
        for (int c = 0; c < 4; c++) a += lp[c] * We[c * HH + h];
        a = fmaxf(a, 0.f);
        se[l4][h] = a;
        g_pool[base + l * HH + h] = a;
        msum += a;
        __syncthreads();
        float su = 0.f, sv = 0.f;
#pragma unroll 8
        for (int k = 0; k < 64; k++) {
            float e = se[l4][k];
            su += e * sw1[k * HH + h];
            sv += e * sw1[(64 + k) * HH + h];
        }
        g_u[base + l * HH + h] = su;
        g_v[base + l * HH + h] = sv;
        __syncthreads();
    }
    sred[l4][h] = msum;
    __syncthreads();
    if (l4 == 0)
        g_means[(b * NN + n) * HH + h] =
            (sred[0][h] + sred[1][h] + sred[2][h] + sred[3][h]) * (1.f / LL);
}

// grid BB, 32 threads
__global__ void k_init_state(const int* __restrict__ order) {
    int b = blockIdx.x, t = threadIdx.x;
    if (t < NN) { g_lsets[b * NN + t] = 1u << t; g_active[b * NN + t] = 1; }
    if (t == 0) {
        g_loss[b] = 0.f;
        unsigned desc[2 * NN - 1];
        for (int n = 0; n < NN; n++) desc[n] = 1u << n;
        for (int s = 0; s < NI; s++) {
            int o0 = order[(b * NI + s) * 2 + 0];
            int o1 = order[(b * NI + s) * 2 + 1];
            unsigned m = desc[o0] | desc[o1];
            desc[NN + s] = m;
            g_clades[b * NI + s] = m;
        }
    }
}

// ---------------- pair score (256 threads, one site per thread) ----------------
__device__ __forceinline__ void score_pair(int b, int i, int j, int p,
                                           const float* __restrict__ bs1,
                                           const float* __restrict__ Ws2,
                                           const float* __restrict__ bs2) {
    __shared__ float sb[64], sw[64], red[256];
    int t = threadIdx.x;
    if (t < 64) { sb[t] = bs1[t]; sw[t] = Ws2[t]; }
    __syncthreads();
    const float* up = g_u + ((size_t)(b * NN + i) * LL + t) * HH;
    const float* vp = g_v + ((size_t)(b * NN + j) * LL + t) * HH;
    float acc = 0.f;
#pragma unroll
    for (int k = 0; k < HH; k += 4) {
        float4 a = *(const float4*)(up + k);
        float4 c = *(const float4*)(vp + k);
        float z;
        z = a.x + c.x + sb[k + 0]; acc += fmaxf(z, 0.f) * sw[k + 0];
        z = a.y + c.y + sb[k + 1]; acc += fmaxf(z, 0.f) * sw[k + 1];
        z = a.z + c.z + sb[k + 2]; acc += fmaxf(z, 0.f) * sw[k + 2];
        z = a.w + c.w + sb[k + 3]; acc += fmaxf(z, 0.f) * sw[k + 3];
    }
    red[t] = acc;
    __syncthreads();
    for (int k = 128; k > 0; k >>= 1) { if (t < k) red[t] += red[t + k]; __syncthreads(); }
    if (t == 0) g_scores[b * PP + p] = red[0] * (1.f / LL) + bs2[0];
}

// grid (PP, BB), 256 threads — step 0 only
__global__ void k_scores_full(const float* __restrict__ bs1, const float* __restrict__ Ws2,
                              const float* __restrict__ bs2) {
    int p = blockIdx.x, b = blockIdx.y;
    int i, j; pdecode(p, i, j);
    score_pair(b, i, j, p, bs1, Ws2, bs2);
}

// grid (NN, BB), 256 threads — rescore only pairs touching last merged slot
__global__ void k_scores_update(const float* __restrict__ bs1, const float* __restrict__ Ws2,
                                const float* __restrict__ bs2) {
    int o = blockIdx.x, b = blockIdx.y;
    int si = g_si[b];
    if (o == si || !g_active[b * NN + o]) return;
    int i = o < si ? o : si;
    int j = o < si ? si : o;
    score_pair(b, i, j, pindex(i, j), bs1, Ws2, bs2);
}

// ---------------- selection + loss + ml output. grid BB, 512 threads ----------------
__global__ void k_select(int s, float* __restrict__ ml) {
    int b = blockIdx.x, t = threadIdx.x;
    __shared__ float red[512];
    __shared__ int s_idx;
    __shared__ float s_max, s_sum, s_cs;
    int i = 0, j = 0, validf = 0;
    unsigned merged = 0;
    float val = -3.0e38f;
    if (t < PP) {
        pdecode(t, i, j);
        validf = g_active[b * NN + i] && g_active[b * NN + j];
        val = validf ? g_scores[b * PP + t] : NEGV;
        ml[((size_t)b * NI + s) * PP + t] = val;
        merged = g_lsets[b * NN + i] | g_lsets[b * NN + j];
    }
    // max
    red[t] = val; __syncthreads();
    for (int k = 256; k > 0; k >>= 1) { if (t < k) red[t] = fmaxf(red[t], red[t + k]); __syncthreads(); }
    if (t == 0) { s_max = red[0]; s_idx = PP; }
    __syncthreads();
    if (t < PP && val == s_max) atomicMin(&s_idx, t);   // first-max index, matches jnp.argmax
    __syncthreads();
    // sum exp
    red[t] = (t < PP) ? expf(val - s_max) : 0.f; __syncthreads();
    for (int k = 256; k > 0; k >>= 1) { if (t < k) red[t] += red[t + k]; __syncthreads(); }
    if (t == 0) s_sum = red[0];
    __syncthreads();
    float logZ = logf(s_sum);
    // cm / cross-entropy
    float cmv = 0.f;
    if (validf) {
        for (int q = 0; q < NI; q++)
            if (merged == g_clades[b * NI + q]) { cmv = 1.f; break; }
    }
    red[t] = cmv; __syncthreads();
    for (int k = 256; k > 0; k >>= 1) { if (t < k) red[t] += red[t + k]; __syncthreads(); }
    if (t == 0) s_cs = red[0];
    __syncthreads();
    red[t] = (cmv > 0.f) ? -(val - s_max - logZ) : 0.f; __syncthreads();
    for (int k = 256; k > 0; k >>= 1) { if (t < k) red[t] += red[t + k]; __syncthreads(); }
    if (t == 0) {
        float cs = s_cs;
        float ce = red[0] / fmaxf(cs, 1.f);
        if (cs > 0.f) g_loss[b] += ce;
        int si, sj; pdecode(s_idx, si, sj);
        g_si[b] = si; g_sj[b] = sj;
        g_lsets[b * NN + si] |= g_lsets[b * NN + sj];
        g_lsets[b * NN + sj] = 0u;
        g_active[b * NN + sj] = 0;
    }
}

// ---------------- parent MLP for the selected pair + pool/u/v update + anc ----------------
// grid (32, BB), 256 threads, 8 sites per block
__global__ void k_parent(int s, const float* __restrict__ Wm1, const float* __restrict__ bm1,
                         const float* __restrict__ Wm2, const float* __restrict__ bm2,
                         const float* __restrict__ Ws1, const float* __restrict__ Wd,
                         const float* __restrict__ bd, float* __restrict__ anc) {
    int b = blockIdx.y;
    int si = g_si[b], sj = g_sj[b];
    int t = threadIdx.x, l4 = t >> 6, h = t & 63;
    __shared__ float sx[4][128];
    __shared__ float sh1[4][64];
    __shared__ float sh2[4][64];
    size_t base_i = ((size_t)(b * NN + si) * LL) * HH;
    size_t base_j = ((size_t)(b * NN + sj) * LL) * HH;
    for (int r = 0; r < 2; r++) {
        int l = blockIdx.x * 8 + r * 4 + l4;
        sx[l4][h]      = g_pool[base_i + l * HH + h];
        sx[l4][64 + h] = g_pool[base_j + l * HH + h];
        __syncthreads();
        float a = bm1[h];
#pragma unroll 4
        for (int k = 0; k < 128; k++) a += sx[l4][k] * Wm1[k * HH + h];
        sh1[l4][h] = fmaxf(a, 0.f);
        __syncthreads();
        float c = bm2[h];
#pragma unroll 4
        for (int k = 0; k < 64; k++) c += sh1[l4][k] * Wm2[k * HH + h];
        c = fmaxf(c, 0.f);
        sh2[l4][h] = c;
        __syncthreads();
        g_pool[base_i + l * HH + h] = c;           // new parent into slot si
        float su = 0.f, sv = 0.f;
#pragma unroll 4
        for (int k = 0; k < 64; k++) {
            float e = sh2[l4][k];
            su += e * Ws1[k * HH + h];
            sv += e * Ws1[(64 + k) * HH + h];
        }
        g_u[base_i + l * HH + h] = su;
        g_v[base_i + l * HH + h] = sv;
        if (h < 4) {
            float av = bd[h];
            for (int k = 0; k < 64; k++) av += sh2[l4][k] * Wd[k * 4 + h];
            anc[(((size_t)b * NI + s) * LL + l) * 4 + h] = av;
        }
        __syncthreads();
    }
}

// ---------------- branch lengths + means update. grid BB, 64 threads ----------------
__global__ void k_branches(int s, const float* __restrict__ Wb1, const float* __restrict__ bb1,
                           const float* __restrict__ Wb2, const float* __restrict__ bb2,
                           float* __restrict__ br) {
    int b = blockIdx.x, h = threadIdx.x;
    int si = g_si[b], sj = g_sj[b];
    __shared__ float spm[64], smi[64], smj[64], red[64];
    const float* pr = g_pool + ((size_t)(b * NN + si) * LL) * HH;
    float acc = 0.f;
#pragma unroll 8
    for (int l = 0; l < LL; l++) acc += pr[l * HH + h];
    float pm = acc * (1.f / LL);
    spm[h] = pm;
    smi[h] = g_means[(b * NN + si) * HH + h];   // OLD mean of slot si
    smj[h] = g_means[(b * NN + sj) * HH + h];
    __syncthreads();
    for (int which = 0; which < 2; which++) {
        const float* mm = which ? smj : smi;
        float a = bb1[h];
#pragma unroll 8
        for (int k = 0; k < 64; k++) a += spm[k] * Wb1[k * HH + h];
#pragma unroll 8
        for (int k = 0; k < 64; k++) a += mm[k] * Wb1[(64 + k) * HH + h];
        a = fmaxf(a, 0.f);
        red[h] = a * Wb2[h];
        __syncthreads();
        for (int k = 32; k > 0; k >>= 1) { if (h < k) red[h] += red[h + k]; __syncthreads(); }
        if (h == 0) {
            float x = red[0] + bb2[0];
            // jax.nn.softplus = max(x,0) + log1p(exp(-|x|))
            br[b * (NI * 2) + 2 * s + which] = fmaxf(x, 0.f) + log1pf(expf(-fabsf(x)));
        }
        __syncthreads();
    }
    g_means[(b * NN + si) * HH + h] = pm;
}

__global__ void k_final(float* __restrict__ lo) {
    lo[0] = (g_loss[0] + g_loss[1] + g_loss[2] + g_loss[3]) * 0.25f;
}

// ---------------- host ----------------
extern "C" void kernel_launch(void* const* d_in, const int* in_sizes, int n_in,
                              void* d_out, int out_size) {
    const float* leaf = (const float*)d_in[0];
    const int*   order = (const int*)d_in[1];
    const float* We  = (const float*)d_in[2];
    const float* be  = (const float*)d_in[3];
    const float* Wm1 = (const float*)d_in[4];
    const float* bm1 = (const float*)d_in[5];
    const float* Wm2 = (const float*)d_in[6];
    const float* bm2 = (const float*)d_in[7];
    const float* Ws1 = (const float*)d_in[8];
    const float* bs1 = (const float*)d_in[9];
    const float* Ws2 = (const float*)d_in[10];
    const float* bs2 = (const float*)d_in[11];
    const float* Wd  = (const float*)d_in[12];
    const float* bd  = (const float*)d_in[13];
    const float* Wb1 = (const float*)d_in[14];
    const float* bb1 = (const float*)d_in[15];
    const float* Wb2 = (const float*)d_in[16];
    const float* bb2 = (const float*)d_in[17];

    float* out = (float*)d_out;
    float* ml  = out;                              // [B, NI, P]
    float* anc = ml + (size_t)BB * NI * PP;        // [B, NI, L, 4]
    float* br  = anc + (size_t)BB * NI * LL * 4;   // [B, NI*2]
    float* lo  = br + (size_t)BB * NI * 2;         // scalar

    k_init_embed<<<dim3(NN, BB), 256>>>(leaf, We, be, Ws1);
    k_init_state<<<BB, 32>>>(order);
    k_scores_full<<<dim3(PP, BB), 256>>>(bs1, Ws2, bs2);
    for (int s = 0; s < NI; s++) {
        if (s) k_scores_update<<<dim3(NN, BB), 256>>>(bs1, Ws2, bs2);
        k_select<<<BB, 512>>>(s, ml);
        k_parent<<<dim3(32, BB), 256>>>(s, Wm1, bm1, Wm2, bm2, Ws1, Wd, bd, anc);
        k_branches<<<BB, 64>>>(s, Wb1, bb1, Wb2, bb2, br);
    }
    k_final<<<1, 1>>>(lo);
}

// round 2
// speedup vs baseline: 1.9294x; 1.9294x over previous
#include <cuda_runtime.h>
#include <math.h>

#define BB 4
#define NN 32
#define LL 256
#define HH 64
#define NI 31
#define PP 496
#define NEGV (-1e9f)
#define BPB 32            // blocks per batch
#define NTHR 256
#define NBAR (1 + 3*NI)   // 94 barriers per batch per launch

// ---------------- persistent device scratch ----------------
__device__ float g_pool[BB*NN*LL*HH];
__device__ float g_u[BB*NN*LL*HH];
__device__ float g_v[BB*NN*LL*HH];
__device__ float g_means[BB*NN*HH];
__device__ float g_scores[BB*PP];
__device__ float g_pmsum[BB*HH];
__device__ unsigned g_lsets[BB*NN];
__device__ int g_active[BB*NN];
__device__ unsigned g_clades[BB*NI];
__device__ int g_si[BB], g_sj[BB];
__device__ float g_loss[BB];
__device__ unsigned g_cnt[BB*32];   // padded to 128B per batch
__device__ unsigned g_gen[BB*32];
__device__ unsigned g_done;

// per-batch software barrier over BPB co-resident blocks (sense = barrier id)
__device__ __forceinline__ void bbar(int b, int id) {
    __syncthreads();
    if (threadIdx.x == 0) {
        unsigned next = (id + 1 == NBAR) ? 0u : (unsigned)(id + 1);
        __threadfence();
        unsigned old = atomicAdd(&g_cnt[b*32], 1u);
        if (old == BPB - 1) {
            g_cnt[b*32] = 0;
            __threadfence();
            atomicExch(&g_gen[b*32], next);
        } else {
            volatile unsigned* gg = &g_gen[b*32];
            while (*gg == (unsigned)id) __nanosleep(32);
        }
        __threadfence();
    }
    __syncthreads();
}

// score one pair (i,j) -> g_scores[b*PP+p]; all 256 threads participate
__device__ __forceinline__ void score_pair(int b, int i, int j, int p,
                                           const float* sbs1, const float* sWs2,
                                           float bs2v, float* red) {
    int t = threadIdx.x;  // site
    const float4* up = (const float4*)(g_u + ((size_t)(b*NN + i)*LL + t)*HH);
    const float4* vp = (const float4*)(g_v + ((size_t)(b*NN + j)*LL + t)*HH);
    float acc = 0.f;
#pragma unroll
    for (int k = 0; k < 16; k++) {
        float4 a = __ldcg(up + k);
        float4 c = __ldcg(vp + k);
        int kk = k * 4;
        float z;
        z = a.x + c.x + sbs1[kk+0]; acc += fmaxf(z, 0.f) * sWs2[kk+0];
        z = a.y + c.y + sbs1[kk+1]; acc += fmaxf(z, 0.f) * sWs2[kk+1];
        z = a.z + c.z + sbs1[kk+2]; acc += fmaxf(z, 0.f) * sWs2[kk+2];
        z = a.w + c.w + sbs1[kk+3]; acc += fmaxf(z, 0.f) * sWs2[kk+3];
    }
    red[t] = acc;
    __syncthreads();
    for (int k = 128; k > 0; k >>= 1) { if (t < k) red[t] += red[t + k]; __syncthreads(); }
    if (t == 0) g_scores[b*PP + p] = red[0] * (1.f / LL) + bs2v;
    __syncthreads();
}

__global__ __launch_bounds__(NTHR, 1)
void phylo_persistent(const float* __restrict__ leaf, const int* __restrict__ order,
                      const float* __restrict__ We, const float* __restrict__ be,
                      const float* __restrict__ Wm1, const float* __restrict__ bm1,
                      const float* __restrict__ Wm2, const float* __restrict__ bm2,
                      const float* __restrict__ Ws1, const float* __restrict__ bs1,
                      const float* __restrict__ Ws2, const float* __restrict__ bs2,
                      const float* __restrict__ Wd, const float* __restrict__ bd,
                      const float* __restrict__ Wb1, const float* __restrict__ bb1,
                      const float* __restrict__ Wb2, const float* __restrict__ bb2,
                      float* __restrict__ ml, float* __restrict__ anc,
                      float* __restrict__ br, float* __restrict__ lo) {
    extern __shared__ float smem[];
    float* sWm1 = smem;                 // 8192
    float* sWm2 = sWm1 + 8192;          // 4096
    float* sWs1 = sWm2 + 4096;          // 8192
    float* sbs1 = sWs1 + 8192;          // 64
    float* sWs2 = sbs1 + 64;            // 64
    float* sbm1 = sWs2 + 64;            // 64
    float* sbm2 = sbm1 + 64;            // 64
    float* se   = sbm2 + 64;            // 1024 (phase A; reused as sx/sh1/sh2 in D)
    float* red  = se + 1024;            // 256
    float* sbr  = red + 256;            // 192: pm, mi, mj
    unsigned char* sPI = (unsigned char*)(sbr + 192);
    unsigned char* sPJ = sPI + PP;

    __shared__ float s_max, s_sum, s_cs, s_ce;
    __shared__ int s_idx;

    const int b = blockIdx.x / BPB;
    const int r = blockIdx.x % BPB;
    const int tid = threadIdx.x;
    int barid = 0;

    // ---- load persistent smem ----
    for (int idx = tid; idx < 128*64; idx += NTHR) sWm1[idx] = Wm1[idx];
    for (int idx = tid; idx < 64*64;  idx += NTHR) sWm2[idx] = Wm2[idx];
    for (int idx = tid; idx < 128*64; idx += NTHR) sWs1[idx] = Ws1[idx];
    if (tid < 64) { sbs1[tid] = bs1[tid]; sWs2[tid] = Ws2[tid];
                    sbm1[tid] = bm1[tid]; sbm2[tid] = bm2[tid]; }
    for (int p = tid; p < PP; p += NTHR) {
        int q = p, ii = 0;
        while (q >= NN - 1 - ii) { q -= NN - 1 - ii; ii++; }
        sPI[p] = (unsigned char)ii; sPJ[p] = (unsigned char)(ii + 1 + q);
    }
    float bs2v = __ldg(&bs2[0]);
    if (r == 0) {
        if (tid < NN) { g_lsets[b*NN + tid] = 1u << tid; g_active[b*NN + tid] = 1; }
        if (tid == 0) {
            g_loss[b] = 0.f;
            unsigned desc[2*NN - 1];
            for (int n = 0; n < NN; n++) desc[n] = 1u << n;
            for (int s = 0; s < NI; s++) {
                unsigned m = desc[order[(b*NI + s)*2]] | desc[order[(b*NI + s)*2 + 1]];
                desc[NN + s] = m;
                g_clades[b*NI + s] = m;
            }
        }
    }
    __syncthreads();

    // ---- Phase A: embed + u/v + mean for node n = r ----
    {
        const int h = tid & 63;
        const size_t nbase = ((size_t)(b*NN + r) * LL) * HH;
        float msum = 0.f;
        for (int st = 0; st < 16; st++) {
            for (int idx = tid; idx < 16*HH; idx += NTHR) {
                int sl = idx >> 6;
                int l = st*16 + sl;
                const float* lp = leaf + (((size_t)(b*NN + r) * LL) + l) * 4;
                float a = __ldg(&be[h]);
#pragma unroll
                for (int c = 0; c < 4; c++) a += lp[c] * __ldg(&We[c*HH + h]);
                a = fmaxf(a, 0.f);
                se[sl*HH + h] = a;
                g_pool[nbase + (size_t)l*HH + h] = a;
                msum += a;
            }
            __syncthreads();
            const int sg = tid >> 6;
            const float* seb = se + (sg*4)*HH;
            float au0=0,au1=0,au2=0,au3=0, av0=0,av1=0,av2=0,av3=0;
#pragma unroll 4
            for (int k = 0; k < HH; k++) {
                float wu = sWs1[k*HH + h];
                float wv = sWs1[(HH + k)*HH + h];
                float e0 = seb[0*HH + k], e1 = seb[1*HH + k];
                float e2 = seb[2*HH + k], e3 = seb[3*HH + k];
                au0 += e0*wu; av0 += e0*wv;
                au1 += e1*wu; av1 += e1*wv;
                au2 += e2*wu; av2 += e2*wv;
                au3 += e3*wu; av3 += e3*wv;
            }
            int l0 = st*16 + sg*4;
            g_u[nbase + (size_t)(l0+0)*HH + h] = au0;
            g_u[nbase + (size_t)(l0+1)*HH + h] = au1;
            g_u[nbase + (size_t)(l0+2)*HH + h] = au2;
            g_u[nbase + (size_t)(l0+3)*HH + h] = au3;
            g_v[nbase + (size_t)(l0+0)*HH + h] = av0;
            g_v[nbase + (size_t)(l0+1)*HH + h] = av1;
            g_v[nbase + (size_t)(l0+2)*HH + h] = av2;
            g_v[nbase + (size_t)(l0+3)*HH + h] = av3;
            __syncthreads();
        }
        red[tid] = msum;
        __syncthreads();
        if (tid < HH)
            g_means[(b*NN + r)*HH + tid] =
                (red[tid] + red[tid+64] + red[tid+128] + red[tid+192]) * (1.f / LL);
        __syncthreads();
    }
    bbar(b, barid++);

    // ---- Phase B: all initial pair scores ----
    for (int p = r; p < PP; p += BPB)
        score_pair(b, sPI[p], sPJ[p], p, sbs1, sWs2, bs2v, red);

    // ---- main sequential loop ----
    for (int s = 0; s < NI; s++) {
        bbar(b, barid++);   // scores ready

        // Phase C: selection (block r==0 only)
        if (r == 0) {
            int t = tid;
            if (t < HH) g_pmsum[b*HH + t] = 0.f;
            float v0, v1 = -3.0e38f;
            int vld0, vld1 = 0;
            unsigned mg0 = 0, mg1 = 0;
            {
                int i = sPI[t], j = sPJ[t];
                vld0 = g_active[b*NN + i] && g_active[b*NN + j];
                v0 = vld0 ? __ldcg(&g_scores[b*PP + t]) : NEGV;
                ml[((size_t)b*NI + s)*PP + t] = v0;
                mg0 = g_lsets[b*NN + i] | g_lsets[b*NN + j];
            }
            if (t < PP - NTHR) {
                int p = t + NTHR;
                int i = sPI[p], j = sPJ[p];
                vld1 = g_active[b*NN + i] && g_active[b*NN + j];
                v1 = vld1 ? __ldcg(&g_scores[b*PP + p]) : NEGV;
                ml[((size_t)b*NI + s)*PP + p] = v1;
                mg1 = g_lsets[b*NN + i] | g_lsets[b*NN + j];
            }
            red[t] = fmaxf(v0, v1);
            __syncthreads();
            for (int k = 128; k > 0; k >>= 1) { if (t < k) red[t] = fmaxf(red[t], red[t+k]); __syncthreads(); }
            if (t == 0) { s_max = red[0]; s_idx = PP; }
            __syncthreads();
            if (v0 == s_max) atomicMin(&s_idx, t);
            if (v1 == s_max) atomicMin(&s_idx, t + NTHR);
            __syncthreads();
            red[t] = expf(v0 - s_max) + ((t < PP - NTHR) ? expf(v1 - s_max) : 0.f);
            __syncthreads();
            for (int k = 128; k > 0; k >>= 1) { if (t < k) red[t] += red[t+k]; __syncthreads(); }
            if (t == 0) s_sum = red[0];
            __syncthreads();
            float logZ = logf(s_sum);
            float cm0 = 0.f, cm1 = 0.f;
            if (vld0) for (int q = 0; q < NI; q++) if (mg0 == g_clades[b*NI + q]) { cm0 = 1.f; break; }
            if (vld1) for (int q = 0; q < NI; q++) if (mg1 == g_clades[b*NI + q]) { cm1 = 1.f; break; }
            red[t] = cm0 + cm1;
            __syncthreads();
            for (int k = 128; k > 0; k >>= 1) { if (t < k) red[t] += red[t+k]; __syncthreads(); }
            if (t == 0) s_cs = red[0];
            __syncthreads();
            red[t] = (cm0 > 0.f ? -(v0 - s_max - logZ) : 0.f)
                   + (cm1 > 0.f ? -(v1 - s_max - logZ) : 0.f);
            __syncthreads();
            for (int k = 128; k > 0; k >>= 1) { if (t < k) red[t] += red[t+k]; __syncthreads(); }
            if (t == 0) {
                if (s_cs > 0.f) g_loss[b] += red[0] / fmaxf(s_cs, 1.f);
                int p = s_idx;
                int si = sPI[p], sj = sPJ[p];
                g_si[b] = si; g_sj[b] = sj;
                g_lsets[b*NN + si] |= g_lsets[b*NN + sj];
                g_lsets[b*NN + sj] = 0u;
                g_active[b*NN + sj] = 0;
            }
            __syncthreads();
        }
        bbar(b, barid++);   // si/sj decided

        // Phase D: parent MLP for 8 sites per block + u/v/pool/anc + pmsum
        {
            int si = __ldcg(&g_si[b]), sj = __ldcg(&g_sj[b]);
            size_t bi = ((size_t)(b*NN + si) * LL) * HH;
            size_t bj = ((size_t)(b*NN + sj) * LL) * HH;
            int l4 = tid >> 6, h = tid & 63;
            float* sx  = se;         // [4][128]
            float* sh1 = se + 512;   // [4][64]
            float* sh2 = se + 768;   // [4][64]
            float psum = 0.f;
            for (int rr = 0; rr < 2; rr++) {
                int l = r*8 + rr*4 + l4;
                sx[l4*128 + h]      = __ldcg(&g_pool[bi + (size_t)l*HH + h]);
                sx[l4*128 + 64 + h] = __ldcg(&g_pool[bj + (size_t)l*HH + h]);
                __syncthreads();
                float a0 = sbm1[h], a1 = 0.f;
#pragma unroll 4
                for (int k = 0; k < 64; k++) {
                    a0 += sx[l4*128 + k]      * sWm1[k*HH + h];
                    a1 += sx[l4*128 + 64 + k] * sWm1[(64 + k)*HH + h];
                }
                sh1[l4*64 + h] = fmaxf(a0 + a1, 0.f);
                __syncthreads();
                float c0 = sbm2[h], c1 = 0.f;
#pragma unroll 4
                for (int k = 0; k < 32; k++) {
                    c0 += sh1[l4*64 + k]      * sWm2[k*HH + h];
                    c1 += sh1[l4*64 + 32 + k] * sWm2[(32 + k)*HH + h];
                }
                float c = fmaxf(c0 + c1, 0.f);
                sh2[l4*64 + h] = c;
                __syncthreads();
                g_pool[bi + (size_t)l*HH + h] = c;
                psum += c;
                float su = 0.f, sv = 0.f;
#pragma unroll 4
                for (int k = 0; k < 64; k++) {
                    float e = sh2[l4*64 + k];
                    su += e * sWs1[k*HH + h];
                    sv += e * sWs1[(64 + k)*HH + h];
                }
                g_u[bi + (size_t)l*HH + h] = su;
                g_v[bi + (size_t)l*HH + h] = sv;
                if (h < 4) {
                    float av = __ldg(&bd[h]);
                    for (int k = 0; k < 64; k++) av += sh2[l4*64 + k] * __ldg(&Wd[k*4 + h]);
                    anc[(((size_t)b*NI + s)*LL + l)*4 + h] = av;
                }
                __syncthreads();
            }
            red[tid] = psum;
            __syncthreads();
            if (l4 == 0)
                atomicAdd(&g_pmsum[b*HH + h], red[h] + red[64+h] + red[128+h] + red[192+h]);
        }
        bbar(b, barid++);   // parent written

        // Phase E: rescore pairs touching si (block r handles other=r) + branches (r==0)
        {
            int si = __ldcg(&g_si[b]);
            int o = r;
            if (o != si && __ldcg(&g_active[b*NN + o])) {
                int i = o < si ? o : si;
                int j = o < si ? si : o;
                int p = i*(2*NN - i - 1)/2 + (j - i - 1);
                score_pair(b, i, j, p, sbs1, sWs2, bs2v, red);
            }
        }
        if (r == 0) {
            int si = __ldcg(&g_si[b]), sj = __ldcg(&g_sj[b]);
            float* spm = sbr;
            float* smi = sbr + 64;
            float* smj = sbr + 128;
            if (tid < HH) {
                spm[tid] = __ldcg(&g_pmsum[b*HH + tid]) * (1.f / LL);
                smi[tid] = g_means[(b*NN + si)*HH + tid];
                smj[tid] = g_means[(b*NN + sj)*HH + tid];
            }
            __syncthreads();
            for (int which = 0; which < 2; which++) {
                float a = 0.f;
                if (tid < HH) {
                    a = __ldg(&bb1[tid]);
                    const float* mm = which ? smj : smi;
#pragma unroll 4
                    for (int k = 0; k < HH; k++) a += spm[k] * __ldg(&Wb1[k*HH + tid]);
#pragma unroll 4
                    for (int k = 0; k < HH; k++) a += mm[k] * __ldg(&Wb1[(HH + k)*HH + tid]);
                    a = fmaxf(a, 0.f) * __ldg(&Wb2[tid]);
                }
                red[tid] = (tid < HH) ? a : 0.f;
                __syncthreads();
                for (int k = 32; k > 0; k >>= 1) { if (tid < k) red[tid] += red[tid + k]; __syncthreads(); }
                if (tid == 0) {
                    float x = red[0] + __ldg(&bb2[0]);
                    br[b*(NI*2) + 2*s + which] = fmaxf(x, 0.f) + log1pf(expf(-fabsf(x)));
                }
                __syncthreads();
            }
            if (tid < HH) g_means[(b*NN + si)*HH + tid] = spm[tid];
        }
    }

    // ---- cross-batch loss aggregation (one arrival per batch) ----
    if (r == 0 && tid == 0) {
        __threadfence();
        unsigned old = atomicAdd(&g_done, 1u);
        if (old == BB - 1) {
            g_done = 0;
            __threadfence();
            lo[0] = (__ldcg(&g_loss[0]) + __ldcg(&g_loss[1]) +
                     __ldcg(&g_loss[2]) + __ldcg(&g_loss[3])) * 0.25f;
        }
    }
}

// ---------------- host ----------------
#define SMEM_BYTES ((22208*4) + 992 + 32)

extern "C" void kernel_launch(void* const* d_in, const int* in_sizes, int n_in,
                              void* d_out, int out_size) {
    const float* leaf = (const float*)d_in[0];
    const int*   order = (const int*)d_in[1];
    const float* We  = (const float*)d_in[2];
    const float* be  = (const float*)d_in[3];
    const float* Wm1 = (const float*)d_in[4];
    const float* bm1 = (const float*)d_in[5];
    const float* Wm2 = (const float*)d_in[6];
    const float* bm2 = (const float*)d_in[7];
    const float* Ws1 = (const float*)d_in[8];
    const float* bs1 = (const float*)d_in[9];
    const float* Ws2 = (const float*)d_in[10];
    const float* bs2 = (const float*)d_in[11];
    const float* Wd  = (const float*)d_in[12];
    const float* bd  = (const float*)d_in[13];
    const float* Wb1 = (const float*)d_in[14];
    const float* bb1 = (const float*)d_in[15];
    const float* Wb2 = (const float*)d_in[16];
    const float* bb2 = (const float*)d_in[17];

    float* out = (float*)d_out;
    float* ml  = out;                              // [B, NI, P]
    float* anc = ml + (size_t)BB * NI * PP;        // [B, NI, L, 4]
    float* br  = anc + (size_t)BB * NI * LL * 4;   // [B, NI*2]
    float* lo  = br + (size_t)BB * NI * 2;         // scalar

    cudaFuncSetAttribute(phylo_persistent,
                         cudaFuncAttributeMaxDynamicSharedMemorySize, SMEM_BYTES);
    phylo_persistent<<<BB*BPB, NTHR, SMEM_BYTES>>>(
        leaf, order, We, be, Wm1, bm1, Wm2, bm2, Ws1, bs1, Ws2, bs2,
        Wd, bd, Wb1, bb1, Wb2, bb2, ml, anc, br, lo);
}

// round 3
// speedup vs baseline: 3.8532x; 1.9971x over previous
#include <cuda_runtime.h>
#include <math.h>

#define BB 4
#define NN 32
#define LL 256
#define HH 64
#define NI 31
#define PP 496
#define NEGV (-1e9f)
#define BPB 32            // blocks per batch; block r owns sites [8r, 8r+8)
#define SB 8              // sites per block
#define NTHR 256
#define NBAR 32           // 1 after init + 31 per-step barriers

// ---------------- persistent device scratch ----------------
__device__ float g_pool[BB*NN*LL*HH];
__device__ float g_u[BB*NN*LL*HH];
__device__ float g_v[BB*NN*LL*HH];
__device__ float g_part[2*BB*PP*BPB];      // per-(parity,b,pair,block) score partials
__device__ float g_pmpart[2*BB*BPB*HH];    // per-(parity,b,block,h) parent-mean partials
__device__ float g_mpart[BB*NN*BPB*HH];    // initial per-node mean partials
__device__ float g_loss[BB];
__device__ unsigned g_cnt[BB*32];
__device__ unsigned g_gen[BB*32];
__device__ unsigned g_done;

// ---------------- smem layout (floats) ----------------
#define OFF_WM1T 0        // 64 x 132
#define OFF_WM2T 8448     // 64 x 68
#define OFF_WS1T 12800    // 64 x 132
#define OFF_WB1T 21248    // 64 x 132
#define OFF_BS1  29696
#define OFF_WS2  29760
#define OFF_BM1  29824
#define OFF_BM2  29888
#define OFF_WD   29952    // 256
#define OFF_BD   30208    // 4 (pad to 30272)
#define OFF_BB1  30272
#define OFF_WB2  30336
#define OFF_SCORE 30400   // 496
#define OFF_RED  30896    // 256
#define OFF_SE   31152    // 1024
#define OFF_UST  32176    // 8 x 68
#define OFF_VST  32720    // 8 x 68
#define OFF_MEANS 33264   // 32 x 64 (block 1 only)
#define SMEM_FLOATS 35312
#define SMEM_BYTES (SMEM_FLOATS*4)

// per-batch software barrier over BPB co-resident blocks
__device__ __forceinline__ void bbar(int b, int id) {
    __syncthreads();
    if (threadIdx.x == 0) {
        unsigned next = (id + 1 == NBAR) ? 0u : (unsigned)(id + 1);
        __threadfence();
        unsigned old = atomicAdd(&g_cnt[b*32], 1u);
        if (old == BPB - 1) {
            g_cnt[b*32] = 0;
            __threadfence();
            atomicExch(&g_gen[b*32], next);
        } else {
            volatile unsigned* gg = &g_gen[b*32];
            while (*gg == (unsigned)id) __nanosleep(20);
        }
        __threadfence();
    }
    __syncthreads();
}

// deferred branch-length computation for step out_step (block 1 only)
__device__ __forceinline__ void do_branch(float* sm, int b, int out_step, int par,
                                          int psi, int psj, float bb2v,
                                          float* __restrict__ br, int t) {
    float* se    = sm + OFF_SE;
    float* red   = sm + OFF_RED;
    float* smean = sm + OFF_MEANS;
    float* sWb1T = sm + OFF_WB1T;
    float* sbb1  = sm + OFF_BB1;
    float* sWb2  = sm + OFF_WB2;
    if (t < HH) {
        const float* pp = g_pmpart + ((size_t)(par*BB + b)*BPB)*HH + t;
        float sum = 0.f;
#pragma unroll 8
        for (int q = 0; q < BPB; q++) sum += __ldcg(pp + q*HH);
        se[t]       = sum * (1.f/LL);   // pm
        se[64 + t]  = smean[psi*HH + t];
        se[128 + t] = smean[psj*HH + t];
    }
    __syncthreads();
    float contrib = 0.f;
    if (t < 128) {
        int which = t >> 6, h = t & 63;
        const float* mm = se + 64 + which*64;
        const float4* wrow = (const float4*)(sWb1T + h*132);
        float a = sbb1[h];
#pragma unroll
        for (int k4 = 0; k4 < 16; k4++) {
            float4 w0 = wrow[k4];
            float4 w1 = wrow[16 + k4];
            float4 x0 = *(const float4*)(se + k4*4);
            float4 x1 = *(const float4*)(mm + k4*4);
            a += x0.x*w0.x + x0.y*w0.y + x0.z*w0.z + x0.w*w0.w;
            a += x1.x*w1.x + x1.y*w1.y + x1.z*w1.z + x1.w*w1.w;
        }
        contrib = fmaxf(a, 0.f) * sWb2[h];
    }
#pragma unroll
    for (int o = 16; o; o >>= 1) contrib += __shfl_xor_sync(0xffffffffu, contrib, o);
    if ((t & 31) == 0) red[t >> 5] = contrib;
    __syncthreads();
    if (t < 2) {
        float x = red[t*2] + red[t*2 + 1] + bb2v;
        br[b*(NI*2) + 2*out_step + t] = fmaxf(x, 0.f) + log1pf(expf(-fabsf(x)));
    }
    if (t < HH) smean[psi*HH + t] = se[t];   // means[si] = pm
    __syncthreads();
}

__global__ __launch_bounds__(NTHR, 1)
void phylo_persistent(const float* __restrict__ leaf, const int* __restrict__ order,
                      const float* __restrict__ We, const float* __restrict__ be,
                      const float* __restrict__ Wm1, const float* __restrict__ bm1,
                      const float* __restrict__ Wm2, const float* __restrict__ bm2,
                      const float* __restrict__ Ws1, const float* __restrict__ bs1,
                      const float* __restrict__ Ws2, const float* __restrict__ bs2,
                      const float* __restrict__ Wd, const float* __restrict__ bd,
                      const float* __restrict__ Wb1, const float* __restrict__ bb1,
                      const float* __restrict__ Wb2, const float* __restrict__ bb2,
                      float* __restrict__ ml, float* __restrict__ anc,
                      float* __restrict__ br, float* __restrict__ lo) {
    extern __shared__ float sm[];
    float* sWm1T = sm + OFF_WM1T;
    float* sWm2T = sm + OFF_WM2T;
    float* sWs1T = sm + OFF_WS1T;
    float* sWb1T = sm + OFF_WB1T;
    float* sbs1  = sm + OFF_BS1;
    float* sWs2  = sm + OFF_WS2;
    float* sbm1  = sm + OFF_BM1;
    float* sbm2  = sm + OFF_BM2;
    float* sWd   = sm + OFF_WD;
    float* sbd   = sm + OFF_BD;
    float* sbb1  = sm + OFF_BB1;
    float* sWb2  = sm + OFF_WB2;
    float* sscore = sm + OFF_SCORE;
    float* red   = sm + OFF_RED;
    float* se    = sm + OFF_SE;
    float* sust  = sm + OFF_UST;
    float* svst  = sm + OFF_VST;

    __shared__ unsigned char sPI[PP], sPJ[PP];
    __shared__ unsigned sclades[NI];
    __shared__ unsigned slset[NN];
    __shared__ int sact[NN];
    __shared__ int s_si, s_sj, s_idx;
    __shared__ float s_loss;

    const int b = blockIdx.x / BPB;
    const int r = blockIdx.x % BPB;
    const int t = threadIdx.x;
    const int lbase = r * SB;
    int barid = 0;

    // ---- load transposed weights + small vectors ----
    for (int idx = t; idx < 128*64; idx += NTHR) {
        int k = idx >> 6, h = idx & 63;
        sWm1T[h*132 + k] = Wm1[idx];
        sWs1T[h*132 + k] = Ws1[idx];
        sWb1T[h*132 + k] = Wb1[idx];
    }
    for (int idx = t; idx < 64*64; idx += NTHR) {
        int k = idx >> 6, h = idx & 63;
        sWm2T[h*68 + k] = Wm2[idx];
    }
    if (t < 64) {
        sbs1[t] = bs1[t]; sWs2[t] = Ws2[t];
        sbm1[t] = bm1[t]; sbm2[t] = bm2[t];
        sbb1[t] = bb1[t]; sWb2[t] = Wb2[t];
    }
    for (int idx = t; idx < 256; idx += NTHR) sWd[idx] = Wd[idx];
    if (t < 4) sbd[t] = bd[t];
    for (int p = t; p < PP; p += NTHR) {
        int q = p, ii = 0;
        while (q >= NN - 1 - ii) { q -= NN - 1 - ii; ii++; }
        sPI[p] = (unsigned char)ii; sPJ[p] = (unsigned char)(ii + 1 + q);
    }
    if (t < NN) { slset[t] = 1u << t; sact[t] = 1; }
    if (t == 0) {
        s_loss = 0.f;
        unsigned desc[2*NN - 1];
        for (int n = 0; n < NN; n++) desc[n] = 1u << n;
        for (int s = 0; s < NI; s++) {
            unsigned m = desc[order[(b*NI + s)*2]] | desc[order[(b*NI + s)*2 + 1]];
            desc[NN + s] = m;
            sclades[s] = m;
        }
    }
    float bs2v = __ldg(&bs2[0]);
    float bb2v = __ldg(&bb2[0]);
    __syncthreads();

    // ---- Phase A: embeds + u/v + mean partials for OWN 8 sites, all 32 nodes ----
    {
        int g = t >> 6, h = t & 63;
        for (int n = 0; n < NN; n++) {
            float ms = 0.f;
#pragma unroll
            for (int pass = 0; pass < 2; pass++) {
                int site = pass*4 + g;
                int l = lbase + site;
                const float* lp = leaf + ((size_t)((b*NN + n)*LL + l))*4;
                float a = __ldg(&be[h]);
#pragma unroll
                for (int c = 0; c < 4; c++) a += __ldg(lp + c) * __ldg(&We[c*HH + h]);
                a = fmaxf(a, 0.f);
                se[site*64 + h] = a;
                g_pool[((size_t)(b*NN + n)*LL + l)*HH + h] = a;
                ms += a;
            }
            red[t] = ms;
            __syncthreads();
            if (g == 0)
                g_mpart[((size_t)(b*NN + n)*BPB + r)*HH + h] =
                    red[h] + red[64 + h] + red[128 + h] + red[192 + h];
            // u/v for sites 2g, 2g+1
            const float* e0p = se + (2*g)*64;
            const float* e1p = se + (2*g + 1)*64;
            const float4* wrow = (const float4*)(sWs1T + h*132);
            float au0 = 0, av0 = 0, au1 = 0, av1 = 0;
#pragma unroll
            for (int k4 = 0; k4 < 16; k4++) {
                float4 wu = wrow[k4];
                float4 wv = wrow[16 + k4];
                float4 e0 = *(const float4*)(e0p + k4*4);
                float4 e1 = *(const float4*)(e1p + k4*4);
                au0 += e0.x*wu.x + e0.y*wu.y + e0.z*wu.z + e0.w*wu.w;
                av0 += e0.x*wv.x + e0.y*wv.y + e0.z*wv.z + e0.w*wv.w;
                au1 += e1.x*wu.x + e1.y*wu.y + e1.z*wu.z + e1.w*wu.w;
                av1 += e1.x*wv.x + e1.y*wv.y + e1.z*wv.z + e1.w*wv.w;
            }
            size_t ub = ((size_t)(b*NN + n)*LL + lbase + 2*g)*HH + h;
            g_u[ub] = au0;       g_v[ub] = av0;
            g_u[ub + HH] = au1;  g_v[ub + HH] = av1;
            __syncthreads();
        }
    }

    // ---- Phase B: initial score partials for all 496 pairs over own sites ----
    for (int rd = 0; rd < 16; rd++) {
        int uidx = rd*NTHR + t;
        int p = uidx >> 3, site = uidx & 7;
        float acc = 0.f;
        if (p < PP) {
            int i = sPI[p], j = sPJ[p];
            const float4* up = (const float4*)(g_u + ((size_t)(b*NN + i)*LL + lbase + site)*HH);
            const float4* vp = (const float4*)(g_v + ((size_t)(b*NN + j)*LL + lbase + site)*HH);
#pragma unroll
            for (int k4 = 0; k4 < 16; k4++) {
                float4 a = up[k4], c = vp[k4];
                int k = k4*4;
                float z;
                z = a.x + c.x + sbs1[k+0]; acc += fmaxf(z, 0.f)*sWs2[k+0];
                z = a.y + c.y + sbs1[k+1]; acc += fmaxf(z, 0.f)*sWs2[k+1];
                z = a.z + c.z + sbs1[k+2]; acc += fmaxf(z, 0.f)*sWs2[k+2];
                z = a.w + c.w + sbs1[k+3]; acc += fmaxf(z, 0.f)*sWs2[k+3];
            }
        }
        acc += __shfl_down_sync(0xffffffffu, acc, 4);
        acc += __shfl_down_sync(0xffffffffu, acc, 2);
        acc += __shfl_down_sync(0xffffffffu, acc, 1);
        if (p < PP && site == 0) g_part[((size_t)(1*BB + b)*PP + p)*32 + r] = acc;
    }
    bbar(b, barid++);   // id 0

    int prev_si = 0, prev_sj = 0;

    // ---- main loop: ONE barrier per step ----
    for (int s = 0; s < NI; s++) {
        // ===== Phase C =====
        if (r == 1) {
            if (s == 0) {
                // build means table from g_mpart
                float* smean = sm + OFF_MEANS;
                for (int idx = t; idx < NN*HH; idx += NTHR) {
                    int n = idx >> 6, h = idx & 63;
                    const float* mp = g_mpart + ((size_t)(b*NN + n)*BPB)*HH + h;
                    float sum = 0.f;
#pragma unroll 8
                    for (int q = 0; q < BPB; q++) sum += __ldcg(mp + q*HH);
                    smean[idx] = sum * (1.f/LL);
                }
                __syncthreads();
            } else {
                do_branch(sm, b, s - 1, (s - 1) & 1, prev_si, prev_sj, bb2v, br, t);
            }
        }

        // finalize scores
        if (s == 0) {
            for (int p = t; p < PP; p += NTHR) {
                const float* gp = g_part + ((size_t)(1*BB + b)*PP + p)*32;
                float sum = 0.f;
#pragma unroll
                for (int q = 0; q < 32; q++) sum += __ldcg(gp + q);
                sscore[p] = sum * (1.f/LL) + bs2v;
            }
        } else {
            int o = t >> 3, q = t & 7;
            int fin = (o != prev_si) && sact[o];
            float ps = 0.f;
            int pidx = 0;
            if (fin) {
                int i = o < prev_si ? o : prev_si;
                int j = o < prev_si ? prev_si : o;
                pidx = i*(2*NN - i - 1)/2 + (j - i - 1);
                const float* gp = g_part + ((size_t)(((s - 1) & 1)*BB + b)*PP + pidx)*32 + q;
                ps = __ldcg(gp) + __ldcg(gp + 8) + __ldcg(gp + 16) + __ldcg(gp + 24);
            }
            ps += __shfl_down_sync(0xffffffffu, ps, 4);
            ps += __shfl_down_sync(0xffffffffu, ps, 2);
            ps += __shfl_down_sync(0xffffffffu, ps, 1);
            if (fin && q == 0) sscore[pidx] = ps * (1.f/LL) + bs2v;
        }
        __syncthreads();

        // selection (replicated, deterministic in every block)
        {
            int i0 = sPI[t], j0 = sPJ[t];
            int vld0 = sact[i0] && sact[j0];
            float v0 = vld0 ? sscore[t] : NEGV;
            unsigned mg0 = slset[i0] | slset[j0];
            int p1 = t + NTHR;
            int vld1 = 0; float v1 = NEGV; unsigned mg1 = 0;
            if (p1 < PP) {
                int i1 = sPI[p1], j1 = sPJ[p1];
                vld1 = sact[i1] && sact[j1];
                v1 = vld1 ? sscore[p1] : NEGV;
                mg1 = slset[i1] | slset[j1];
            }
            if (r == 0) {
                ml[((size_t)b*NI + s)*PP + t] = v0;
                if (p1 < PP) ml[((size_t)b*NI + s)*PP + p1] = v1;
            }
            float m = fmaxf(v0, v1);
#pragma unroll
            for (int o = 16; o; o >>= 1) m = fmaxf(m, __shfl_xor_sync(0xffffffffu, m, o));
            if ((t & 31) == 0) red[t >> 5] = m;
            __syncthreads();
            if (t < 32) {
                float mm = (t < 8) ? red[t] : -3.0e38f;
#pragma unroll
                for (int o = 4; o; o >>= 1) mm = fmaxf(mm, __shfl_xor_sync(0xffffffffu, mm, o));
                if (t == 0) { red[0] = mm; s_idx = PP; }
            }
            __syncthreads();
            float vmax = red[0];
            if (v0 == vmax) atomicMin(&s_idx, t);
            if (p1 < PP && v1 == vmax) atomicMin(&s_idx, p1);
            float cm0 = 0.f, cm1 = 0.f;
            if (vld0) { for (int q = 0; q < NI; q++) if (mg0 == sclades[q]) { cm0 = 1.f; break; } }
            if (vld1) { for (int q = 0; q < NI; q++) if (mg1 == sclades[q]) { cm1 = 1.f; break; } }
            float esum = expf(v0 - vmax) + ((p1 < PP) ? expf(v1 - vmax) : 0.f);
            float csv = cm0 + cm1;
            float av  = cm0 * (vmax - v0) + cm1 * (vmax - v1);
#pragma unroll
            for (int o = 16; o; o >>= 1) {
                esum += __shfl_xor_sync(0xffffffffu, esum, o);
                csv  += __shfl_xor_sync(0xffffffffu, csv, o);
                av   += __shfl_xor_sync(0xffffffffu, av, o);
            }
            if ((t & 31) == 0) {
                red[8  + (t >> 5)] = esum;
                red[16 + (t >> 5)] = csv;
                red[24 + (t >> 5)] = av;
            }
            __syncthreads();
            if (t == 0) {
                float S = 0, C = 0, A = 0;
                for (int w = 0; w < 8; w++) { S += red[8+w]; C += red[16+w]; A += red[24+w]; }
                float logz = logf(S);
                float ce = (A + logz * C) / fmaxf(C, 1.f);
                if (r == 0 && C > 0.f) s_loss += ce;
                int sel = s_idx;
                int si = sPI[sel], sj = sPJ[sel];
                s_si = si; s_sj = sj;
                slset[si] |= slset[sj];
                slset[sj] = 0u;
                sact[sj] = 0;
            }
            __syncthreads();
        }

        // ===== Phase D: parent MLP for own 8 sites =====
        {
            int si = s_si, sj = s_sj;
            size_t bi = ((size_t)(b*NN + si)*LL)*HH;
            size_t bj = ((size_t)(b*NN + sj)*LL)*HH;
            int l4 = t >> 6, h = t & 63;
            float* sx  = se;        // [4][128]
            float* sh1 = se + 512;  // [4][64]
            float* sh2 = se + 768;  // [4][64]
            float psum = 0.f;
            for (int rr = 0; rr < 2; rr++) {
                int site = rr*4 + l4;
                int l = lbase + site;
                sx[l4*128 + h]      = g_pool[bi + (size_t)l*HH + h];
                sx[l4*128 + 64 + h] = g_pool[bj + (size_t)l*HH + h];
                __syncthreads();
                const float4* w1r = (const float4*)(sWm1T + h*132);
                const float4* xr  = (const float4*)(sx + l4*128);
                float a = sbm1[h];
#pragma unroll
                for (int k4 = 0; k4 < 32; k4++) {
                    float4 w = w1r[k4];
                    float4 x = xr[k4];
                    a += x.x*w.x + x.y*w.y + x.z*w.z + x.w*w.w;
                }
                sh1[l4*64 + h] = fmaxf(a, 0.f);
                __syncthreads();
                const float4* w2r = (const float4*)(sWm2T + h*68);
                const float4* h1r = (const float4*)(sh1 + l4*64);
                float c = sbm2[h];
#pragma unroll
                for (int k4 = 0; k4 < 16; k4++) {
                    float4 w = w2r[k4];
                    float4 x = h1r[k4];
                    c += x.x*w.x + x.y*w.y + x.z*w.z + x.w*w.w;
                }
                c = fmaxf(c, 0.f);
                sh2[l4*64 + h] = c;
                __syncthreads();
                g_pool[bi + (size_t)l*HH + h] = c;
                psum += c;
                const float4* wsr = (const float4*)(sWs1T + h*132);
                const float4* h2r = (const float4*)(sh2 + l4*64);
                float su = 0.f, sv = 0.f;
#pragma unroll
                for (int k4 = 0; k4 < 16; k4++) {
                    float4 wu = wsr[k4];
                    float4 wv = wsr[16 + k4];
                    float4 x = h2r[k4];
                    su += x.x*wu.x + x.y*wu.y + x.z*wu.z + x.w*wu.w;
                    sv += x.x*wv.x + x.y*wv.y + x.z*wv.z + x.w*wv.w;
                }
                sust[site*68 + h] = su;
                svst[site*68 + h] = sv;
                g_u[bi + (size_t)l*HH + h] = su;
                g_v[bi + (size_t)l*HH + h] = sv;
                if (h < 4) {
                    float av2 = sbd[h];
#pragma unroll 4
                    for (int k = 0; k < 64; k++) av2 += sh2[l4*64 + k] * sWd[k*4 + h];
                    anc[(((size_t)b*NI + s)*LL + l)*4 + h] = av2;
                }
                __syncthreads();
            }
            red[t] = psum;
            __syncthreads();
            if (l4 == 0)
                g_pmpart[((size_t)((s & 1)*BB + b)*BPB + r)*HH + h] =
                    red[h] + red[64 + h] + red[128 + h] + red[192 + h];
            __syncthreads();
        }

        // ===== Phase E: rescore partials for pairs touching si, own sites =====
        {
            int si = s_si;
            int o = t >> 3, site = t & 7;
            int doit = sact[o] && (o != si);
            float acc = 0.f;
            int pidx = 0;
            if (doit) {
                int i = o < si ? o : si;
                int j = o < si ? si : o;
                pidx = i*(2*NN - i - 1)/2 + (j - i - 1);
                const float* stp = ((o < si) ? svst : sust) + site*68;
                const float4* gop = (const float4*)(((o < si) ? g_u : g_v) +
                                    ((size_t)(b*NN + o)*LL + lbase + site)*HH);
#pragma unroll
                for (int k4 = 0; k4 < 16; k4++) {
                    float4 gv = gop[k4];
                    float4 sv4 = *(const float4*)(stp + k4*4);
                    int k = k4*4;
                    float z;
                    z = gv.x + sv4.x + sbs1[k+0]; acc += fmaxf(z, 0.f)*sWs2[k+0];
                    z = gv.y + sv4.y + sbs1[k+1]; acc += fmaxf(z, 0.f)*sWs2[k+1];
                    z = gv.z + sv4.z + sbs1[k+2]; acc += fmaxf(z, 0.f)*sWs2[k+2];
                    z = gv.w + sv4.w + sbs1[k+3]; acc += fmaxf(z, 0.f)*sWs2[k+3];
                }
            }
            acc += __shfl_down_sync(0xffffffffu, acc, 4);
            acc += __shfl_down_sync(0xffffffffu, acc, 2);
            acc += __shfl_down_sync(0xffffffffu, acc, 1);
            if (doit && site == 0)
                g_part[((size_t)((s & 1)*BB + b)*PP + pidx)*32 + r] = acc;
        }

        prev_si = s_si; prev_sj = s_sj;
        bbar(b, barid++);   // ids 1..31, wraps to 0 after last
    }

    // ---- epilogue ----
    if (r == 1)
        do_branch(sm, b, NI - 1, (NI - 1) & 1, prev_si, prev_sj, bb2v, br, t);
    if (r == 0 && t == 0) {
        g_loss[b] = s_loss;
        __threadfence();
        unsigned old = atomicAdd(&g_done, 1u);
        if (old == BB - 1) {
            g_done = 0;
            __threadfence();
            lo[0] = 0.25f * (__ldcg(&g_loss[0]) + __ldcg(&g_loss[1]) +
                             __ldcg(&g_loss[2]) + __ldcg(&g_loss[3]));
        }
    }
}

// ---------------- host ----------------
extern "C" void kernel_launch(void* const* d_in, const int* in_sizes, int n_in,
                              void* d_out, int out_size) {
    const float* leaf = (const float*)d_in[0];
    const int*   order = (const int*)d_in[1];
    const float* We  = (const float*)d_in[2];
    const float* be  = (const float*)d_in[3];
    const float* Wm1 = (const float*)d_in[4];
    const float* bm1 = (const float*)d_in[5];
    const float* Wm2 = (const float*)d_in[6];
    const float* bm2 = (const float*)d_in[7];
    const float* Ws1 = (const float*)d_in[8];
    const float* bs1 = (const float*)d_in[9];
    const float* Ws2 = (const float*)d_in[10];
    const float* bs2 = (const float*)d_in[11];
    const float* Wd  = (const float*)d_in[12];
    const float* bd  = (const float*)d_in[13];
    const float* Wb1 = (const float*)d_in[14];
    const float* bb1 = (const float*)d_in[15];
    const float* Wb2 = (const float*)d_in[16];
    const float* bb2 = (const float*)d_in[17];

    float* out = (float*)d_out;
    float* ml  = out;                              // [B, NI, P]
    float* anc = ml + (size_t)BB * NI * PP;        // [B, NI, L, 4]
    float* br  = anc + (size_t)BB * NI * LL * 4;   // [B, NI*2]
    float* lo  = br + (size_t)BB * NI * 2;         // scalar

    cudaFuncSetAttribute(phylo_persistent,
                         cudaFuncAttributeMaxDynamicSharedMemorySize, SMEM_BYTES);
    phylo_persistent<<<BB*BPB, NTHR, SMEM_BYTES>>>(
        leaf, order, We, be, Wm1, bm1, Wm2, bm2, Ws1, bs1, Ws2, bs2,
        Wd, bd, Wb1, bb1, Wb2, bb2, ml, anc, br, lo);
}

// round 4
// speedup vs baseline: 4.1774x; 1.0841x over previous
#include <cuda_runtime.h>
#include <math.h>

#define BB 4
#define NN 32
#define LL 256
#define HH 64
#define NI 31
#define PP 496
#define NEGV (-1e9f)
#define BPB 32            // blocks per batch; block r owns sites [8r, 8r+8)
#define SB 8
#define NTHR 512
#define NBAR 32

// ---------------- persistent device scratch ----------------
__device__ float g_pool[BB*NN*LL*HH];
__device__ float g_u[BB*NN*LL*HH];
__device__ float g_v[BB*NN*LL*HH];
__device__ float g_part[2*BB*PP*BPB];      // per-(parity,b,pair,block) score partials
__device__ float g_pmpart[2*BB*BPB*HH];    // per-(parity,b,block,h) parent-mean partials
__device__ float g_mpart[BB*NN*BPB*HH];    // initial per-node mean partials
__device__ float g_loss[BB];
__device__ unsigned g_cnt[BB*32];
__device__ unsigned g_gen[BB*32];
__device__ unsigned g_done;

// ---------------- smem layout (floats) ----------------
#define OFF_WM1T 0        // 64 x 132
#define OFF_WM2T 8448     // 64 x 68
#define OFF_WS1T 12800    // 64 x 132
#define OFF_WB1T 21248    // 64 x 132
#define OFF_BS1  29696
#define OFF_WS2  29760
#define OFF_BM1  29824
#define OFF_BM2  29888
#define OFF_WD   29952    // 64x4
#define OFF_BD   30208    // 4 (pad 64)
#define OFF_BB1  30272
#define OFF_WB2  30336
#define OFF_SCORE 30400   // 496 (pad 512)
#define OFF_RED  30912    // 512
#define OFF_SX   31424    // 8 x 128
#define OFF_SH1  32448    // 8 x 64
#define OFF_SH2  32960    // 8 x 64
#define OFF_UST  33472    // 8 x 68
#define OFF_VST  34016    // 8 x 68
#define OFF_MEANS 34560   // 32 x 64 (block r==1 only)
#define OFF_WE   36608    // 4 x 64
#define OFF_BE   36864    // 64
#define SMEM_FLOATS 36928
#define SMEM_BYTES (SMEM_FLOATS*4)

// per-batch software barrier over BPB co-resident blocks
__device__ __forceinline__ void bbar(int b, int id) {
    __syncthreads();
    if (threadIdx.x == 0) {
        unsigned next = (id + 1 == NBAR) ? 0u : (unsigned)(id + 1);
        __threadfence();
        unsigned old = atomicAdd(&g_cnt[b*32], 1u);
        if (old == BPB - 1) {
            g_cnt[b*32] = 0;
            __threadfence();
            atomicExch(&g_gen[b*32], next);
        } else {
            volatile unsigned* gg = &g_gen[b*32];
            while (*gg == (unsigned)id) __nanosleep(20);
        }
        __threadfence();
    }
    __syncthreads();
}

// deferred branch-length computation for step out_step (block r==1 only)
__device__ __forceinline__ void do_branch(float* sm, int b, int out_step, int par,
                                          int psi, int psj, float bb2v,
                                          float* __restrict__ br, int t) {
    float* se    = sm + OFF_SX;     // reuse sx region as scratch (192 floats)
    float* red   = sm + OFF_RED;
    float* smean = sm + OFF_MEANS;
    float* sWb1T = sm + OFF_WB1T;
    float* sbb1  = sm + OFF_BB1;
    float* sWb2  = sm + OFF_WB2;
    // parallel pm reduction: 256 threads, h = t&63, group g = t>>6 sums 8 partials
    if (t < 256) {
        int h = t & 63, g = t >> 6;
        const float* pp = g_pmpart + ((size_t)(par*BB + b)*BPB + g*8)*HH + h;
        float a0 = __ldcg(pp) + __ldcg(pp + HH);
        float a1 = __ldcg(pp + 2*HH) + __ldcg(pp + 3*HH);
        float a2 = __ldcg(pp + 4*HH) + __ldcg(pp + 5*HH);
        float a3 = __ldcg(pp + 6*HH) + __ldcg(pp + 7*HH);
        red[t] = (a0 + a1) + (a2 + a3);
    }
    __syncthreads();
    if (t < HH) {
        se[t]       = (red[t] + red[64 + t] + red[128 + t] + red[192 + t]) * (1.f/LL);
        se[64 + t]  = smean[psi*HH + t];
        se[128 + t] = smean[psj*HH + t];
    }
    __syncthreads();
    float contrib = 0.f;
    if (t < 128) {
        int which = t >> 6, h = t & 63;
        const float* mm = se + 64 + which*64;
        const float4* wrow = (const float4*)(sWb1T + h*132);
        float a0 = 0, a1 = 0, a2 = 0, a3 = 0;
#pragma unroll
        for (int k4 = 0; k4 < 16; k4++) {
            float4 w0 = wrow[k4];
            float4 w1 = wrow[16 + k4];
            float4 x0 = *(const float4*)(se + k4*4);
            float4 x1 = *(const float4*)(mm + k4*4);
            a0 += x0.x*w0.x; a1 += x0.y*w0.y; a2 += x0.z*w0.z; a3 += x0.w*w0.w;
            a0 += x1.x*w1.x; a1 += x1.y*w1.y; a2 += x1.z*w1.z; a3 += x1.w*w1.w;
        }
        float a = sbb1[h] + ((a0 + a1) + (a2 + a3));
        contrib = fmaxf(a, 0.f) * sWb2[h];
    }
#pragma unroll
    for (int o = 16; o; o >>= 1) contrib += __shfl_xor_sync(0xffffffffu, contrib, o);
    if (t < 128 && (t & 31) == 0) red[256 + (t >> 5)] = contrib;
    __syncthreads();
    if (t < 2) {
        float x = red[256 + t*2] + red[256 + t*2 + 1] + bb2v;
        br[b*(NI*2) + 2*out_step + t] = fmaxf(x, 0.f) + log1pf(expf(-fabsf(x)));
    }
    if (t < HH) smean[psi*HH + t] = se[t];
    __syncthreads();
}

__global__ __launch_bounds__(NTHR, 1)
void phylo_persistent(const float* __restrict__ leaf, const int* __restrict__ order,
                      const float* __restrict__ We, const float* __restrict__ be,
                      const float* __restrict__ Wm1, const float* __restrict__ bm1,
                      const float* __restrict__ Wm2, const float* __restrict__ bm2,
                      const float* __restrict__ Ws1, const float* __restrict__ bs1,
                      const float* __restrict__ Ws2, const float* __restrict__ bs2,
                      const float* __restrict__ Wd, const float* __restrict__ bd,
                      const float* __restrict__ Wb1, const float* __restrict__ bb1,
                      const float* __restrict__ Wb2, const float* __restrict__ bb2,
                      float* __restrict__ ml, float* __restrict__ anc,
                      float* __restrict__ br, float* __restrict__ lo) {
    extern __shared__ float sm[];
    float* sWm1T = sm + OFF_WM1T;
    float* sWm2T = sm + OFF_WM2T;
    float* sWs1T = sm + OFF_WS1T;
    float* sWb1T = sm + OFF_WB1T;
    float* sbs1  = sm + OFF_BS1;
    float* sWs2  = sm + OFF_WS2;
    float* sbm1  = sm + OFF_BM1;
    float* sbm2  = sm + OFF_BM2;
    float* sWd   = sm + OFF_WD;
    float* sbd   = sm + OFF_BD;
    float* sbb1  = sm + OFF_BB1;
    float* sWb2  = sm + OFF_WB2;
    float* sscore = sm + OFF_SCORE;
    float* red   = sm + OFF_RED;
    float* sx    = sm + OFF_SX;
    float* sh1   = sm + OFF_SH1;
    float* sh2   = sm + OFF_SH2;
    float* sust  = sm + OFF_UST;
    float* svst  = sm + OFF_VST;
    float* sWe   = sm + OFF_WE;
    float* sbe   = sm + OFF_BE;

    __shared__ unsigned char sPI[PP], sPJ[PP];
    __shared__ unsigned sclades[NI];
    __shared__ unsigned slset[NN];
    __shared__ int sact[NN];
    __shared__ int s_si, s_sj, s_idx;
    __shared__ float s_loss, s_vmax;

    const int b = blockIdx.x / BPB;
    const int r = blockIdx.x % BPB;
    const int t = threadIdx.x;
    const int lbase = r * SB;
    int barid = 0;

    // ---- load transposed weights + small vectors ----
    for (int idx = t; idx < 128*64; idx += NTHR) {
        int k = idx >> 6, h = idx & 63;
        sWm1T[h*132 + k] = Wm1[idx];
        sWs1T[h*132 + k] = Ws1[idx];
        sWb1T[h*132 + k] = Wb1[idx];
    }
    for (int idx = t; idx < 64*64; idx += NTHR) {
        int k = idx >> 6, h = idx & 63;
        sWm2T[h*68 + k] = Wm2[idx];
    }
    if (t < 64) {
        sbs1[t] = bs1[t]; sWs2[t] = Ws2[t];
        sbm1[t] = bm1[t]; sbm2[t] = bm2[t];
        sbb1[t] = bb1[t]; sWb2[t] = Wb2[t];
        sbe[t]  = be[t];
    }
    for (int idx = t; idx < 256; idx += NTHR) { sWd[idx] = Wd[idx]; sWe[idx] = We[idx]; }
    if (t < 4) sbd[t] = bd[t];
    for (int p = t; p < PP; p += NTHR) {
        int q = p, ii = 0;
        while (q >= NN - 1 - ii) { q -= NN - 1 - ii; ii++; }
        sPI[p] = (unsigned char)ii; sPJ[p] = (unsigned char)(ii + 1 + q);
    }
    if (t < NN) { slset[t] = 1u << t; sact[t] = 1; }
    if (t == 0) {
        s_loss = 0.f;
        unsigned desc[2*NN - 1];
        for (int n = 0; n < NN; n++) desc[n] = 1u << n;
        for (int s = 0; s < NI; s++) {
            unsigned m = desc[order[(b*NI + s)*2]] | desc[order[(b*NI + s)*2 + 1]];
            desc[NN + s] = m;
            sclades[s] = m;
        }
    }
    float bs2v = __ldg(&bs2[0]);
    float bb2v = __ldg(&bb2[0]);
    __syncthreads();

    // ---- Phase A: embeds + u/v + mean partials for OWN 8 sites, all 32 nodes ----
    {
        const int site = t >> 6, h = t & 63;
        const int l = lbase + site;
        for (int n = 0; n < NN; n++) {
            const float4 lf = __ldg((const float4*)(leaf + ((size_t)((b*NN + n)*LL + l))*4));
            float a = sbe[h] + lf.x*sWe[h] + lf.y*sWe[64 + h]
                            + lf.z*sWe[128 + h] + lf.w*sWe[192 + h];
            a = fmaxf(a, 0.f);
            sx[site*64 + h] = a;     // reuse sx as 8x64 embed buffer
            red[t] = a;
            g_pool[((size_t)(b*NN + n)*LL + l)*HH + h] = a;
            __syncthreads();
            if (t < 64)
                g_mpart[((size_t)(b*NN + n)*BPB + r)*HH + t] =
                    ((red[t] + red[64+t]) + (red[128+t] + red[192+t])) +
                    ((red[256+t] + red[320+t]) + (red[384+t] + red[448+t]));
            const float4* ep = (const float4*)(sx + site*64);
            const float4* wrow = (const float4*)(sWs1T + h*132);
            float u0=0,u1=0,u2=0,u3=0, v0=0,v1=0,v2=0,v3=0;
#pragma unroll
            for (int k4 = 0; k4 < 16; k4++) {
                float4 wu = wrow[k4];
                float4 wv = wrow[16 + k4];
                float4 e = ep[k4];
                u0 += e.x*wu.x; u1 += e.y*wu.y; u2 += e.z*wu.z; u3 += e.w*wu.w;
                v0 += e.x*wv.x; v1 += e.y*wv.y; v2 += e.z*wv.z; v3 += e.w*wv.w;
            }
            size_t ub = ((size_t)(b*NN + n)*LL + l)*HH + h;
            g_u[ub] = (u0 + u1) + (u2 + u3);
            g_v[ub] = (v0 + v1) + (v2 + v3);
            __syncthreads();
        }
    }

    // ---- Phase B: initial score partials for all 496 pairs over own sites ----
    for (int rd = 0; rd < 8; rd++) {
        int uidx = rd*NTHR + t;
        int p = uidx >> 3, site = uidx & 7;
        float acc = 0.f;
        if (p < PP) {
            int i = sPI[p], j = sPJ[p];
            const float4* up = (const float4*)(g_u + ((size_t)(b*NN + i)*LL + lbase + site)*HH);
            const float4* vp = (const float4*)(g_v + ((size_t)(b*NN + j)*LL + lbase + site)*HH);
            float c0=0,c1=0,c2=0,c3=0;
#pragma unroll
            for (int k4 = 0; k4 < 16; k4++) {
                float4 a = up[k4], c = vp[k4];
                int k = k4*4;
                c0 += fmaxf(a.x + c.x + sbs1[k+0], 0.f)*sWs2[k+0];
                c1 += fmaxf(a.y + c.y + sbs1[k+1], 0.f)*sWs2[k+1];
                c2 += fmaxf(a.z + c.z + sbs1[k+2], 0.f)*sWs2[k+2];
                c3 += fmaxf(a.w + c.w + sbs1[k+3], 0.f)*sWs2[k+3];
            }
            acc = (c0 + c1) + (c2 + c3);
        }
        acc += __shfl_down_sync(0xffffffffu, acc, 4);
        acc += __shfl_down_sync(0xffffffffu, acc, 2);
        acc += __shfl_down_sync(0xffffffffu, acc, 1);
        if (p < PP && site == 0) g_part[((size_t)(1*BB + b)*PP + p)*32 + r] = acc;
    }
    bbar(b, barid++);   // id 0

    int prev_si = 0, prev_sj = 0;

    // ---- main loop: ONE global barrier per step ----
    for (int s = 0; s < NI; s++) {
        // ===== block r==1 housekeeping (branches / means) =====
        if (r == 1) {
            if (s == 0) {
                float* smean = sm + OFF_MEANS;
                for (int idx = t; idx < NN*HH; idx += NTHR) {
                    int n = idx >> 6, h = idx & 63;
                    const float* mp = g_mpart + ((size_t)(b*NN + n)*BPB)*HH + h;
                    float a0=0,a1=0,a2=0,a3=0;
#pragma unroll
                    for (int q = 0; q < 32; q += 4) {
                        a0 += __ldcg(mp + q*HH);
                        a1 += __ldcg(mp + (q+1)*HH);
                        a2 += __ldcg(mp + (q+2)*HH);
                        a3 += __ldcg(mp + (q+3)*HH);
                    }
                    smean[idx] = ((a0+a1)+(a2+a3)) * (1.f/LL);
                }
                __syncthreads();
            } else {
                do_branch(sm, b, s - 1, (s - 1) & 1, prev_si, prev_sj, bb2v, br, t);
            }
        }

        // ===== finalize scores =====
        if (s == 0) {
            for (int p = t; p < PP; p += NTHR) {
                const float* gp = g_part + ((size_t)(1*BB + b)*PP + p)*32;
                float a0=0,a1=0,a2=0,a3=0;
#pragma unroll
                for (int q = 0; q < 32; q += 4) {
                    a0 += __ldcg(gp + q);   a1 += __ldcg(gp + q + 1);
                    a2 += __ldcg(gp + q+2); a3 += __ldcg(gp + q + 3);
                }
                sscore[p] = ((a0+a1)+(a2+a3)) * (1.f/LL) + bs2v;
            }
        } else {
            int o = t >> 4, q = t & 15;
            int fin = (o != prev_si) && sact[o];
            float ps = 0.f;
            int pidx = 0;
            if (fin) {
                int i = o < prev_si ? o : prev_si;
                int j = o < prev_si ? prev_si : o;
                pidx = i*(2*NN - i - 1)/2 + (j - i - 1);
                const float* gp = g_part + ((size_t)(((s - 1) & 1)*BB + b)*PP + pidx)*32 + q;
                ps = __ldcg(gp) + __ldcg(gp + 16);
            }
            ps += __shfl_down_sync(0xffffffffu, ps, 8);
            ps += __shfl_down_sync(0xffffffffu, ps, 4);
            ps += __shfl_down_sync(0xffffffffu, ps, 2);
            ps += __shfl_down_sync(0xffffffffu, ps, 1);
            if (fin && q == 0) sscore[pidx] = ps * (1.f/LL) + bs2v;
        }
        __syncthreads();

        // ===== selection (replicated, deterministic) =====
        {
            float v = NEGV;
            int vld = 0;
            unsigned mg = 0;
            unsigned long long key = 0ULL;
            if (t < PP) {
                int i = sPI[t], j = sPJ[t];
                vld = sact[i] && sact[j];
                v = vld ? sscore[t] : NEGV;
                mg = slset[i] | slset[j];
                unsigned ub = __float_as_uint(v);
                ub = (ub & 0x80000000u) ? ~ub : (ub | 0x80000000u);
                key = ((unsigned long long)ub << 32) | (unsigned)(PP - t);
                if (r == 0) ml[((size_t)b*NI + s)*PP + t] = v;
            }
#pragma unroll
            for (int o = 16; o; o >>= 1) {
                unsigned long long ok = __shfl_xor_sync(0xffffffffu, key, o);
                if (ok > key) key = ok;
            }
            unsigned long long* redk = (unsigned long long*)red;
            if ((t & 31) == 0) redk[t >> 5] = key;
            __syncthreads();
            if (t == 0) {
                unsigned long long mk = redk[0];
#pragma unroll
                for (int w = 1; w < 16; w++) if (redk[w] > mk) mk = redk[w];
                s_idx = PP - (int)(mk & 0xffffffffu);
                unsigned u = (unsigned)(mk >> 32);
                unsigned bits = (u & 0x80000000u) ? (u ^ 0x80000000u) : ~u;
                s_vmax = __uint_as_float(bits);
            }
            __syncthreads();
            float vmax = s_vmax;
            float e = (t < PP) ? expf(v - vmax) : 0.f;
            float cm = 0.f;
            if (vld) { for (int q = 0; q < NI; q++) if (mg == sclades[q]) { cm = 1.f; break; } }
            float av = cm * (vmax - v);
#pragma unroll
            for (int o = 16; o; o >>= 1) {
                e  += __shfl_xor_sync(0xffffffffu, e, o);
                cm += __shfl_xor_sync(0xffffffffu, cm, o);
                av += __shfl_xor_sync(0xffffffffu, av, o);
            }
            if ((t & 31) == 0) {
                int w = t >> 5;
                red[32 + w] = e; red[64 + w] = cm; red[96 + w] = av;
            }
            __syncthreads();
            if (t == 0) {
                float S = 0, C = 0, A = 0;
#pragma unroll
                for (int w = 0; w < 16; w++) { S += red[32+w]; C += red[64+w]; A += red[96+w]; }
                float logz = logf(S);
                if (r == 0 && C > 0.f) s_loss += (A + logz * C) / fmaxf(C, 1.f);
                int sel = s_idx;
                int si = sPI[sel], sj = sPJ[sel];
                s_si = si; s_sj = sj;
                slset[si] |= slset[sj];
                slset[sj] = 0u;
                sact[sj] = 0;
            }
            __syncthreads();
        }

        const int si = s_si, sj = s_sj;

        // ===== Phase D: parent MLP, single pass (8 sites x 64 h) =====
        float cval;
        {
            size_t bi = ((size_t)(b*NN + si)*LL)*HH;
            size_t bj = ((size_t)(b*NN + sj)*LL)*HH;
            int site = t >> 6, h = t & 63;
            int l = lbase + site;
            sx[site*128 + h]      = g_pool[bi + (size_t)l*HH + h];
            sx[site*128 + 64 + h] = g_pool[bj + (size_t)l*HH + h];
            __syncthreads();
            {
                const float4* w1r = (const float4*)(sWm1T + h*132);
                const float4* xr  = (const float4*)(sx + site*128);
                float a0=0,a1=0,a2=0,a3=0;
#pragma unroll
                for (int k4 = 0; k4 < 32; k4++) {
                    float4 w = w1r[k4];
                    float4 x = xr[k4];
                    a0 += x.x*w.x; a1 += x.y*w.y; a2 += x.z*w.z; a3 += x.w*w.w;
                }
                sh1[site*64 + h] = fmaxf(sbm1[h] + ((a0+a1)+(a2+a3)), 0.f);
            }
            __syncthreads();
            {
                const float4* w2r = (const float4*)(sWm2T + h*68);
                const float4* h1r = (const float4*)(sh1 + site*64);
                float a0=0,a1=0,a2=0,a3=0;
#pragma unroll
                for (int k4 = 0; k4 < 16; k4++) {
                    float4 w = w2r[k4];
                    float4 x = h1r[k4];
                    a0 += x.x*w.x; a1 += x.y*w.y; a2 += x.z*w.z; a3 += x.w*w.w;
                }
                cval = fmaxf(sbm2[h] + ((a0+a1)+(a2+a3)), 0.f);
            }
            sh2[site*64 + h] = cval;
            red[t] = cval;
            __syncthreads();
            g_pool[bi + (size_t)l*HH + h] = cval;
            {
                const float4* wsr = (const float4*)(sWs1T + h*132);
                const float4* h2r = (const float4*)(sh2 + site*64);
                float u0=0,u1=0,u2=0,u3=0, v0=0,v1=0,v2=0,v3=0;
#pragma unroll
                for (int k4 = 0; k4 < 16; k4++) {
                    float4 wu = wsr[k4];
                    float4 wv = wsr[16 + k4];
                    float4 x = h2r[k4];
                    u0 += x.x*wu.x; u1 += x.y*wu.y; u2 += x.z*wu.z; u3 += x.w*wu.w;
                    v0 += x.x*wv.x; v1 += x.y*wv.y; v2 += x.z*wv.z; v3 += x.w*wv.w;
                }
                float su = (u0+u1)+(u2+u3), sv = (v0+v1)+(v2+v3);
                sust[site*68 + h] = su;
                svst[site*68 + h] = sv;
                g_u[bi + (size_t)l*HH + h] = su;
                g_v[bi + (size_t)l*HH + h] = sv;
            }
            __syncthreads();   // sust/svst + sh2 + red ready for E / anc / pmpart
        }

        // ===== Phase E: rescore partials for pairs touching si, own sites =====
        {
            int o = t >> 4, site = (t >> 1) & 7, half = t & 1;
            int doit = sact[o] && (o != si);
            float acc = 0.f;
            int pidx = 0;
            if (doit) {
                int i = o < si ? o : si;
                int j = o < si ? si : o;
                pidx = i*(2*NN - i - 1)/2 + (j - i - 1);
                const float4* stp = (const float4*)(((o < si) ? svst : sust) + site*68);
                const float4* gop = (const float4*)(((o < si) ? g_u : g_v) +
                                    ((size_t)(b*NN + o)*LL + lbase + site)*HH);
                float c0=0,c1=0,c2=0,c3=0;
#pragma unroll
                for (int q = 0; q < 8; q++) {
                    int k4 = half*8 + q;
                    float4 gv = gop[k4];
                    float4 sv4 = stp[k4];
                    int k = k4*4;
                    c0 += fmaxf(gv.x + sv4.x + sbs1[k+0], 0.f)*sWs2[k+0];
                    c1 += fmaxf(gv.y + sv4.y + sbs1[k+1], 0.f)*sWs2[k+1];
                    c2 += fmaxf(gv.z + sv4.z + sbs1[k+2], 0.f)*sWs2[k+2];
                    c3 += fmaxf(gv.w + sv4.w + sbs1[k+3], 0.f)*sWs2[k+3];
                }
                acc = (c0+c1)+(c2+c3);
            }
            acc += __shfl_down_sync(0xffffffffu, acc, 1);
            acc += __shfl_down_sync(0xffffffffu, acc, 2);
            acc += __shfl_down_sync(0xffffffffu, acc, 4);
            acc += __shfl_down_sync(0xffffffffu, acc, 8);
            if (doit && (t & 15) == 0)
                g_part[((size_t)((s & 1)*BB + b)*PP + pidx)*32 + r] = acc;
        }

        // ===== anc output (reads sh2, off critical path) =====
        if (t < 32) {
            int site = t >> 2, ch = t & 3;
            const float* h2 = sh2 + site*64;
            float a0=0,a1=0,a2=0,a3=0;
#pragma unroll
            for (int k = 0; k < 64; k += 4) {
                a0 += h2[k]   * sWd[k*4 + ch];
                a1 += h2[k+1] * sWd[(k+1)*4 + ch];
                a2 += h2[k+2] * sWd[(k+2)*4 + ch];
                a3 += h2[k+3] * sWd[(k+3)*4 + ch];
            }
            anc[(((size_t)b*NI + s)*LL + lbase + site)*4 + ch] =
                sbd[ch] + ((a0+a1)+(a2+a3));
        }
        // ===== pmpart (reads red, written in D) =====
        else if (t >= 64 && t < 128) {
            int h = t - 64;
            g_pmpart[((size_t)((s & 1)*BB + b)*BPB + r)*HH + h] =
                ((red[h] + red[64+h]) + (red[128+h] + red[192+h])) +
                ((red[256+h] + red[320+h]) + (red[384+h] + red[448+h]));
        }

        prev_si = si; prev_sj = sj;
        bbar(b, barid++);   // ids 1..31, wraps to 0 after last
    }

    // ---- epilogue ----
    if (r == 1)
        do_branch(sm, b, NI - 1, (NI - 1) & 1, prev_si, prev_sj, bb2v, br, t);
    if (r == 0 && t == 0) {
        g_loss[b] = s_loss;
        __threadfence();
        unsigned old = atomicAdd(&g_done, 1u);
        if (old == BB - 1) {
            g_done = 0;
            __threadfence();
            lo[0] = 0.25f * (__ldcg(&g_loss[0]) + __ldcg(&g_loss[1]) +
                             __ldcg(&g_loss[2]) + __ldcg(&g_loss[3]));
        }
    }
}

// ---------------- host ----------------
extern "C" void kernel_launch(void* const* d_in, const int* in_sizes, int n_in,
                              void* d_out, int out_size) {
    const float* leaf = (const float*)d_in[0];
    const int*   order = (const int*)d_in[1];
    const float* We  = (const float*)d_in[2];
    const float* be  = (const float*)d_in[3];
    const float* Wm1 = (const float*)d_in[4];
    const float* bm1 = (const float*)d_in[5];
    const float* Wm2 = (const float*)d_in[6];
    const float* bm2 = (const float*)d_in[7];
    const float* Ws1 = (const float*)d_in[8];
    const float* bs1 = (const float*)d_in[9];
    const float* Ws2 = (const float*)d_in[10];
    const float* bs2 = (const float*)d_in[11];
    const float* Wd  = (const float*)d_in[12];
    const float* bd  = (const float*)d_in[13];
    const float* Wb1 = (const float*)d_in[14];
    const float* bb1 = (const float*)d_in[15];
    const float* Wb2 = (const float*)d_in[16];
    const float* bb2 = (const float*)d_in[17];

    float* out = (float*)d_out;
    float* ml  = out;                              // [B, NI, P]
    float* anc = ml + (size_t)BB * NI * PP;        // [B, NI, L, 4]
    float* br  = anc + (size_t)BB * NI * LL * 4;   // [B, NI*2]
    float* lo  = br + (size_t)BB * NI * 2;         // scalar

    cudaFuncSetAttribute(phylo_persistent,
                         cudaFuncAttributeMaxDynamicSharedMemorySize, SMEM_BYTES);
    phylo_persistent<<<BB*BPB, NTHR, SMEM_BYTES>>>(
        leaf, order, We, be, Wm1, bm1, Wm2, bm2, Ws1, bs1, Ws2, bs2,
        Wd, bd, Wb1, bb1, Wb2, bb2, ml, anc, br, lo);
}

// round 5
// speedup vs baseline: 4.3770x; 1.0478x over previous
#include <cuda_runtime.h>
#include <math.h>

#define BB 4
#define NN 32
#define LL 256
#define HH 64
#define NI 31
#define PP 496
#define NEGV (-1e9f)
#define BPB 32            // blocks per batch; block r owns sites [8r, 8r+8)
#define SB 8
#define NTHR 512
#define NBAR 32

// ---------------- persistent device scratch ----------------
__device__ float g_pool[BB*NN*LL*HH];
__device__ float g_u[BB*NN*LL*HH];
__device__ float g_v[BB*NN*LL*HH];
__device__ float g_part[2*BB*PP*BPB];
__device__ float g_pmpart[2*BB*BPB*HH];
__device__ float g_mpart[BB*NN*BPB*HH];
__device__ float g_loss[BB];
__device__ unsigned g_cnt[BB*32];
__device__ unsigned g_gen[BB*32];
__device__ unsigned g_done;

// ---------------- smem layout (floats) ----------------
#define OFF_WM1T 0        // 64 x 132
#define OFF_WM2T 8448     // 64 x 68
#define OFF_WS1T 12800    // 64 x 132
#define OFF_WB1T 21248    // 64 x 132
#define OFF_BS1  29696
#define OFF_WS2  29760
#define OFF_BM1  29824
#define OFF_BM2  29888
#define OFF_WD   29952    // 64x4
#define OFF_BD   30208
#define OFF_BB1  30272
#define OFF_WB2  30336
#define OFF_SCORE 30400   // 496 pad 512
#define OFF_RED  30912    // 512
#define OFF_SX   31424    // 8 x 132
#define OFF_SH1  32480    // 8 x 68
#define OFF_SH2  33024    // 8 x 68
#define OFF_UST  33568    // 8 x 68
#define OFF_VST  34112    // 8 x 68
#define OFF_MEANS 34656   // 32 x 64 (block r==1)
#define OFF_WE   36704    // 4 x 64
#define OFF_BE   36960    // 64
#define OFF_BSTG 37024    // 256 (branch pm stage / r0 unused)
#define OFF_BSE  37280    // 192 (branch pm/mi/mj)
#define OFF_BRED 37472    // 32  (branch + loss warp partials)
#define SMEM_FLOATS 37504
#define SMEM_BYTES (SMEM_FLOATS*4)

#define BAR1 asm volatile("bar.sync 1, 256;" ::: "memory")
#define BAR2 asm volatile("bar.sync 2, 256;" ::: "memory")
#define ARR3 asm volatile("bar.arrive 3, 512;" ::: "memory")
#define SYN3 asm volatile("bar.sync 3, 512;" ::: "memory")

// f32x2 packed-FP32 helpers (FFMA2): exact per-lane rn arithmetic
__device__ __forceinline__ void ffma2(unsigned long long& acc, unsigned long long a,
                                      unsigned long long b) {
    asm("fma.rn.f32x2 %0, %1, %2, %0;" : "+l"(acc) : "l"(a), "l"(b));
}
__device__ __forceinline__ float f2sum(unsigned long long a, unsigned long long b) {
    float ax, ay, bx, by;
    asm("mov.b64 {%0,%1}, %2;" : "=f"(ax), "=f"(ay) : "l"(a));
    asm("mov.b64 {%0,%1}, %2;" : "=f"(bx), "=f"(by) : "l"(b));
    return (ax + ay) + (bx + by);
}

// per-batch software barrier over BPB co-resident blocks
__device__ __forceinline__ void bbar(int b, int id) {
    __syncthreads();
    if (threadIdx.x == 0) {
        unsigned next = (id + 1 == NBAR) ? 0u : (unsigned)(id + 1);
        __threadfence();
        unsigned old = atomicAdd(&g_cnt[b*32], 1u);
        if (old == BPB - 1) {
            g_cnt[b*32] = 0;
            __threadfence();
            atomicExch(&g_gen[b*32], next);
        } else {
            volatile unsigned* gg = &g_gen[b*32];
            while (*gg == (unsigned)id) __nanosleep(20);
        }
        __threadfence();
    }
    __syncthreads();
}

// deferred branch lengths for out_step; runs on warps 8-15 of block r==1 (tt = t-256)
__device__ __forceinline__ void do_branch(float* sm, int b, int out_step, int par,
                                          int psi, int psj, float bb2v,
                                          float* __restrict__ br, int tt) {
    float* stage = sm + OFF_BSTG;
    float* se2   = sm + OFF_BSE;
    float* bred  = sm + OFF_BRED;
    float* smean = sm + OFF_MEANS;
    float* sWb1T = sm + OFF_WB1T;
    float* sbb1  = sm + OFF_BB1;
    float* sWb2  = sm + OFF_WB2;
    {
        int h = tt & 63, g = tt >> 6;
        const float* pp = g_pmpart + ((size_t)(par*BB + b)*BPB + g*8)*HH + h;
        float a0 = __ldcg(pp) + __ldcg(pp + HH);
        float a1 = __ldcg(pp + 2*HH) + __ldcg(pp + 3*HH);
        float a2 = __ldcg(pp + 4*HH) + __ldcg(pp + 5*HH);
        float a3 = __ldcg(pp + 6*HH) + __ldcg(pp + 7*HH);
        stage[tt] = (a0 + a1) + (a2 + a3);
    }
    BAR2;
    if (tt < HH) {
        se2[tt]       = (stage[tt] + stage[64+tt] + stage[128+tt] + stage[192+tt]) * (1.f/LL);
        se2[64 + tt]  = smean[psi*HH + tt];
        se2[128 + tt] = smean[psj*HH + tt];
    }
    BAR2;
    float contrib = 0.f;
    if (tt < 128) {
        int which = tt >> 6, h = tt & 63;
        const float* mm = se2 + 64 + which*64;
        const float4* wrow = (const float4*)(sWb1T + h*132);
        float a0 = 0, a1 = 0, a2 = 0, a3 = 0;
#pragma unroll
        for (int k4 = 0; k4 < 16; k4++) {
            float4 w0 = wrow[k4];
            float4 w1 = wrow[16 + k4];
            float4 x0 = *(const float4*)(se2 + k4*4);
            float4 x1 = *(const float4*)(mm + k4*4);
            a0 += x0.x*w0.x; a1 += x0.y*w0.y; a2 += x0.z*w0.z; a3 += x0.w*w0.w;
            a0 += x1.x*w1.x; a1 += x1.y*w1.y; a2 += x1.z*w1.z; a3 += x1.w*w1.w;
        }
        float a = sbb1[h] + ((a0 + a1) + (a2 + a3));
        contrib = fmaxf(a, 0.f) * sWb2[h];
    }
#pragma unroll
    for (int o = 16; o; o >>= 1) contrib += __shfl_xor_sync(0xffffffffu, contrib, o);
    if (tt < 128 && (tt & 31) == 0) bred[tt >> 5] = contrib;
    BAR2;
    if (tt < 2) {
        float x = bred[tt*2] + bred[tt*2 + 1] + bb2v;
        br[b*(NI*2) + 2*out_step + tt] = fmaxf(x, 0.f) + log1pf(expf(-fabsf(x)));
    }
    if (tt < HH) smean[psi*HH + tt] = se2[tt];
}

__global__ __launch_bounds__(NTHR, 1)
void phylo_persistent(const float* __restrict__ leaf, const int* __restrict__ order,
                      const float* __restrict__ We, const float* __restrict__ be,
                      const float* __restrict__ Wm1, const float* __restrict__ bm1,
                      const float* __restrict__ Wm2, const float* __restrict__ bm2,
                      const float* __restrict__ Ws1, const float* __restrict__ bs1,
                      const float* __restrict__ Ws2, const float* __restrict__ bs2,
                      const float* __restrict__ Wd, const float* __restrict__ bd,
                      const float* __restrict__ Wb1, const float* __restrict__ bb1,
                      const float* __restrict__ Wb2, const float* __restrict__ bb2,
                      float* __restrict__ ml, float* __restrict__ anc,
                      float* __restrict__ br, float* __restrict__ lo) {
    extern __shared__ float sm[];
    float* sWm1T = sm + OFF_WM1T;
    float* sWm2T = sm + OFF_WM2T;
    float* sWs1T = sm + OFF_WS1T;
    float* sWb1T = sm + OFF_WB1T;
    float* sbs1  = sm + OFF_BS1;
    float* sWs2  = sm + OFF_WS2;
    float* sbm1  = sm + OFF_BM1;
    float* sbm2  = sm + OFF_BM2;
    float* sWd   = sm + OFF_WD;
    float* sbd   = sm + OFF_BD;
    float* sscore = sm + OFF_SCORE;
    float* red   = sm + OFF_RED;
    float* sx    = sm + OFF_SX;
    float* sh1   = sm + OFF_SH1;
    float* sh2   = sm + OFF_SH2;
    float* sust  = sm + OFF_UST;
    float* svst  = sm + OFF_VST;
    float* sWe   = sm + OFF_WE;
    float* sbe   = sm + OFF_BE;
    float* bred  = sm + OFF_BRED;

    __shared__ unsigned char sPI[PP], sPJ[PP];
    __shared__ unsigned sclades[NI];
    __shared__ unsigned slset[NN];
    __shared__ int sact[NN];
    __shared__ int s_si, s_sj;
    __shared__ float s_loss, s_vmax;

    const int b = blockIdx.x / BPB;
    const int r = blockIdx.x % BPB;
    const int t = threadIdx.x;
    const int lbase = r * SB;
    int barid = 0;

    // ---- load transposed weights + small vectors ----
    for (int idx = t; idx < 128*64; idx += NTHR) {
        int k = idx >> 6, h = idx & 63;
        sWm1T[h*132 + k] = Wm1[idx];
        sWs1T[h*132 + k] = Ws1[idx];
        sWb1T[h*132 + k] = Wb1[idx];
    }
    for (int idx = t; idx < 64*64; idx += NTHR) {
        int k = idx >> 6, h = idx & 63;
        sWm2T[h*68 + k] = Wm2[idx];
    }
    if (t < 64) {
        sbs1[t] = bs1[t]; sWs2[t] = Ws2[t];
        sbm1[t] = bm1[t]; sbm2[t] = bm2[t];
        (sm + OFF_BB1)[t] = bb1[t]; (sm + OFF_WB2)[t] = Wb2[t];
        sbe[t]  = be[t];
    }
    for (int idx = t; idx < 256; idx += NTHR) { sWd[idx] = Wd[idx]; sWe[idx] = We[idx]; }
    if (t < 4) sbd[t] = bd[t];
    for (int p = t; p < PP; p += NTHR) {
        int q = p, ii = 0;
        while (q >= NN - 1 - ii) { q -= NN - 1 - ii; ii++; }
        sPI[p] = (unsigned char)ii; sPJ[p] = (unsigned char)(ii + 1 + q);
    }
    if (t < NN) { slset[t] = 1u << t; sact[t] = 1; }
    if (t == 0) {
        s_loss = 0.f;
        unsigned desc[2*NN - 1];
        for (int n = 0; n < NN; n++) desc[n] = 1u << n;
        for (int s = 0; s < NI; s++) {
            unsigned m = desc[order[(b*NI + s)*2]] | desc[order[(b*NI + s)*2 + 1]];
            desc[NN + s] = m;
            sclades[s] = m;
        }
    }
    float bs2v = __ldg(&bs2[0]);
    float bb2v = __ldg(&bb2[0]);
    __syncthreads();

    const int site = t >> 6, h = t & 63;    // (site, h) load/store mapping
    const int gh = t >> 3, gs = t & 7;      // (h, site) GEMM mapping
    const int l = lbase + site;
    const int gl = lbase + gs;

    // ---- Phase A: embeds + u/v + mean partials for own 8 sites, all 32 nodes ----
    for (int n = 0; n < NN; n++) {
        size_t nb = ((size_t)(b*NN + n)*LL)*HH;
        const float4 lf = __ldg((const float4*)(leaf + ((size_t)(b*NN + n)*LL + l)*4));
        float a = fmaxf(sbe[h] + lf.x*sWe[h] + lf.y*sWe[64+h]
                               + lf.z*sWe[128+h] + lf.w*sWe[192+h], 0.f);
        sx[site*132 + h] = a;
        red[t] = a;
        __syncthreads();
        if (t < 64)
            g_mpart[((size_t)(b*NN + n)*BPB + r)*HH + t] =
                ((red[t] + red[64+t]) + (red[128+t] + red[192+t])) +
                ((red[256+t] + red[320+t]) + (red[384+t] + red[448+t]));
        {
            const ulonglong2* w = (const ulonglong2*)(sWs1T + gh*132);
            const ulonglong2* x = (const ulonglong2*)(sx + gs*132);
            unsigned long long uA=0,uB=0,vA=0,vB=0;
#pragma unroll
            for (int k4 = 0; k4 < 16; k4++) {
                ulonglong2 wu = w[k4];
                ulonglong2 wv = w[16 + k4];
                ulonglong2 xv = x[k4];
                ffma2(uA, wu.x, xv.x); ffma2(uB, wu.y, xv.y);
                ffma2(vA, wv.x, xv.x); ffma2(vB, wv.y, xv.y);
            }
            sust[gs*68 + gh] = f2sum(uA, uB);
            svst[gs*68 + gh] = f2sum(vA, vB);
        }
        __syncthreads();
        size_t ub = nb + (size_t)l*HH + h;
        g_pool[ub] = a;
        g_u[ub] = sust[site*68 + h];
        g_v[ub] = svst[site*68 + h];
        __syncthreads();
    }

    // ---- Phase B: initial score partials ----
    for (int rd = 0; rd < 8; rd++) {
        int uidx = rd*NTHR + t;
        int p = uidx >> 3, st8 = uidx & 7;
        float acc = 0.f;
        if (p < PP) {
            int i = sPI[p], j = sPJ[p];
            const float4* up = (const float4*)(g_u + ((size_t)(b*NN + i)*LL + lbase + st8)*HH);
            const float4* vp = (const float4*)(g_v + ((size_t)(b*NN + j)*LL + lbase + st8)*HH);
            float c0=0,c1=0,c2=0,c3=0;
#pragma unroll
            for (int k4 = 0; k4 < 16; k4++) {
                float4 a = up[k4], c = vp[k4];
                int k = k4*4;
                c0 += fmaxf(a.x + c.x + sbs1[k+0], 0.f)*sWs2[k+0];
                c1 += fmaxf(a.y + c.y + sbs1[k+1], 0.f)*sWs2[k+1];
                c2 += fmaxf(a.z + c.z + sbs1[k+2], 0.f)*sWs2[k+2];
                c3 += fmaxf(a.w + c.w + sbs1[k+3], 0.f)*sWs2[k+3];
            }
            acc = (c0 + c1) + (c2 + c3);
        }
        acc += __shfl_down_sync(0xffffffffu, acc, 4);
        acc += __shfl_down_sync(0xffffffffu, acc, 2);
        acc += __shfl_down_sync(0xffffffffu, acc, 1);
        if (p < PP && st8 == 0) g_part[((size_t)(1*BB + b)*PP + p)*32 + r] = acc;
    }
    bbar(b, barid++);

    int prev_si = 0, prev_sj = 0;

    // ---- main loop: one global barrier per step ----
    for (int s = 0; s < NI; s++) {
        if (t < 256) {
            // ===== warps 0-7: finalize + argmax =====
            if (s == 0) {
                for (int p = t; p < PP; p += 256) {
                    const float* gp = g_part + ((size_t)(1*BB + b)*PP + p)*32;
                    float a0=0,a1=0,a2=0,a3=0;
#pragma unroll
                    for (int q = 0; q < 32; q += 4) {
                        a0 += __ldcg(gp + q);     a1 += __ldcg(gp + q + 1);
                        a2 += __ldcg(gp + q + 2); a3 += __ldcg(gp + q + 3);
                    }
                    sscore[p] = ((a0+a1)+(a2+a3)) * (1.f/LL) + bs2v;
                }
            } else {
                int o = t >> 3, q = t & 7;
                int fin = (o != prev_si) && sact[o];
                float ps = 0.f;
                int pidx = 0;
                if (fin) {
                    int i = o < prev_si ? o : prev_si;
                    int j = o < prev_si ? prev_si : o;
                    pidx = i*(2*NN - i - 1)/2 + (j - i - 1);
                    const float* gp = g_part + ((size_t)(((s-1) & 1)*BB + b)*PP + pidx)*32 + q;
                    ps = (__ldcg(gp) + __ldcg(gp + 8)) + (__ldcg(gp + 16) + __ldcg(gp + 24));
                }
                ps += __shfl_down_sync(0xffffffffu, ps, 4);
                ps += __shfl_down_sync(0xffffffffu, ps, 2);
                ps += __shfl_down_sync(0xffffffffu, ps, 1);
                if (fin && q == 0) sscore[pidx] = ps * (1.f/LL) + bs2v;
            }
            BAR1;
            // argmax over 496 via packed keys (2 pairs per thread)
            unsigned long long key;
            {
                int i0 = sPI[t], j0 = sPJ[t];
                float v0 = (sact[i0] && sact[j0]) ? sscore[t] : NEGV;
                unsigned ub0 = __float_as_uint(v0);
                ub0 = (ub0 & 0x80000000u) ? ~ub0 : (ub0 | 0x80000000u);
                key = ((unsigned long long)ub0 << 32) | (unsigned)(PP - t);
                int p1 = t + 256;
                if (p1 < PP) {
                    int i1 = sPI[p1], j1 = sPJ[p1];
                    float v1 = (sact[i1] && sact[j1]) ? sscore[p1] : NEGV;
                    unsigned ub1 = __float_as_uint(v1);
                    ub1 = (ub1 & 0x80000000u) ? ~ub1 : (ub1 | 0x80000000u);
                    unsigned long long k1 = ((unsigned long long)ub1 << 32) | (unsigned)(PP - p1);
                    if (k1 > key) key = k1;
                }
            }
#pragma unroll
            for (int o = 16; o; o >>= 1) {
                unsigned long long ok = __shfl_xor_sync(0xffffffffu, key, o);
                if (ok > key) key = ok;
            }
            unsigned long long* redk = (unsigned long long*)red;
            if ((t & 31) == 0) redk[t >> 5] = key;
            BAR1;
            if (t < 8) {
                unsigned long long k = redk[t];
#pragma unroll
                for (int o = 4; o; o >>= 1) {
                    unsigned long long ok = __shfl_xor_sync(0xffu, k, o);
                    if (ok > k) k = ok;
                }
                if (t == 0) {
                    int sel = PP - (int)(k & 0xffffffffu);
                    unsigned u = (unsigned)(k >> 32);
                    unsigned bits = (u & 0x80000000u) ? (u ^ 0x80000000u) : ~u;
                    s_vmax = __uint_as_float(bits);
                    s_si = sPI[sel]; s_sj = sPJ[sel];
                }
            }
            if (r == 0) ARR3;
        } else {
            int tt = t - 256;
            if (r == 1) {
                // ===== warps 8-15 of block 1: means (s==0) or deferred branch =====
                if (s == 0) {
                    float* smean = sm + OFF_MEANS;
                    for (int idx = tt; idx < NN*HH; idx += 256) {
                        int n = idx >> 6, hh = idx & 63;
                        const float* mp = g_mpart + ((size_t)(b*NN + n)*BPB)*HH + hh;
                        float a0=0,a1=0,a2=0,a3=0;
#pragma unroll
                        for (int q = 0; q < 32; q += 4) {
                            a0 += __ldcg(mp + q*HH);       a1 += __ldcg(mp + (q+1)*HH);
                            a2 += __ldcg(mp + (q+2)*HH);   a3 += __ldcg(mp + (q+3)*HH);
                        }
                        smean[idx] = ((a0+a1)+(a2+a3)) * (1.f/LL);
                    }
                } else {
                    do_branch(sm, b, s - 1, (s - 1) & 1, prev_si, prev_sj, bb2v, br, tt);
                }
            } else if (r == 0) {
                // ===== warps 8-15 of block 0: ml + loss for step s =====
                SYN3;
                float vmax = s_vmax;
                float e, cm, av;
                {
                    int i0 = sPI[tt], j0 = sPJ[tt];
                    int vld0 = sact[i0] && sact[j0];
                    float v0 = vld0 ? sscore[tt] : NEGV;
                    ml[((size_t)b*NI + s)*PP + tt] = v0;
                    unsigned mg0 = slset[i0] | slset[j0];
                    float cm0 = 0.f;
                    if (vld0) { for (int q = 0; q < NI; q++) if (mg0 == sclades[q]) { cm0 = 1.f; break; } }
                    e = expf(v0 - vmax); cm = cm0; av = cm0 * (vmax - v0);
                    int p1 = tt + 256;
                    if (p1 < PP) {
                        int i1 = sPI[p1], j1 = sPJ[p1];
                        int vld1 = sact[i1] && sact[j1];
                        float v1 = vld1 ? sscore[p1] : NEGV;
                        ml[((size_t)b*NI + s)*PP + p1] = v1;
                        unsigned mg1 = slset[i1] | slset[j1];
                        float cm1 = 0.f;
                        if (vld1) { for (int q = 0; q < NI; q++) if (mg1 == sclades[q]) { cm1 = 1.f; break; } }
                        e += expf(v1 - vmax); cm += cm1; av += cm1 * (vmax - v1);
                    }
                }
#pragma unroll
                for (int o = 16; o; o >>= 1) {
                    e  += __shfl_xor_sync(0xffffffffu, e, o);
                    cm += __shfl_xor_sync(0xffffffffu, cm, o);
                    av += __shfl_xor_sync(0xffffffffu, av, o);
                }
                if ((tt & 31) == 0) {
                    int w = tt >> 5;
                    bred[w] = e; bred[8 + w] = cm; bred[16 + w] = av;
                }
                BAR2;
                if (tt == 0) {
                    float S = 0, C = 0, A = 0;
#pragma unroll
                    for (int w = 0; w < 8; w++) { S += bred[w]; C += bred[8+w]; A += bred[16+w]; }
                    float logz = logf(S);
                    if (C > 0.f) s_loss += (A + logz * C) / fmaxf(C, 1.f);
                }
            }
        }
        __syncthreads();   // join; s_si/s_sj visible

        const int si = s_si, sj = s_sj;
        const size_t bi = ((size_t)(b*NN + si)*LL)*HH;
        const size_t bj = ((size_t)(b*NN + sj)*LL)*HH;

        // ===== Phase D: parent MLP (single pass, h-major GEMMs, FFMA2) =====
        sx[site*132 + h]      = g_pool[bi + (size_t)l*HH + h];
        sx[site*132 + 64 + h] = g_pool[bj + (size_t)l*HH + h];
        if (t == 0) {
            slset[si] |= slset[sj];
            slset[sj] = 0u;
            sact[sj] = 0;
        }
        __syncthreads();
        {
            const ulonglong2* w = (const ulonglong2*)(sWm1T + gh*132);
            const ulonglong2* x = (const ulonglong2*)(sx + gs*132);
            unsigned long long aA = 0, aB = 0;
#pragma unroll
            for (int k4 = 0; k4 < 32; k4++) {
                ulonglong2 wv = w[k4], xv = x[k4];
                ffma2(aA, wv.x, xv.x); ffma2(aB, wv.y, xv.y);
            }
            sh1[gs*68 + gh] = fmaxf(sbm1[gh] + f2sum(aA, aB), 0.f);
        }
        __syncthreads();
        {
            const ulonglong2* w = (const ulonglong2*)(sWm2T + gh*68);
            const ulonglong2* x = (const ulonglong2*)(sh1 + gs*68);
            unsigned long long aA = 0, aB = 0;
#pragma unroll
            for (int k4 = 0; k4 < 16; k4++) {
                ulonglong2 wv = w[k4], xv = x[k4];
                ffma2(aA, wv.x, xv.x); ffma2(aB, wv.y, xv.y);
            }
            float cval = fmaxf(sbm2[gh] + f2sum(aA, aB), 0.f);
            sh2[gs*68 + gh] = cval;
            g_pool[bi + (size_t)gl*HH + gh] = cval;
        }
        __syncthreads();
        {
            const ulonglong2* w = (const ulonglong2*)(sWs1T + gh*132);
            const ulonglong2* x = (const ulonglong2*)(sh2 + gs*68);
            unsigned long long uA=0,uB=0,vA=0,vB=0;
#pragma unroll
            for (int k4 = 0; k4 < 16; k4++) {
                ulonglong2 wu = w[k4];
                ulonglong2 wv = w[16 + k4];
                ulonglong2 xv = x[k4];
                ffma2(uA, wu.x, xv.x); ffma2(uB, wu.y, xv.y);
                ffma2(vA, wv.x, xv.x); ffma2(vB, wv.y, xv.y);
            }
            float su = f2sum(uA, uB), sv = f2sum(vA, vB);
            sust[gs*68 + gh] = su;
            svst[gs*68 + gh] = sv;
            g_u[bi + (size_t)gl*HH + gh] = su;
            g_v[bi + (size_t)gl*HH + gh] = sv;
        }
        __syncthreads();

        // ===== Phase E: rescore partials for pairs touching si =====
        {
            int o = t >> 4, es = (t >> 1) & 7, half = t & 1;
            int doit = sact[o] && (o != si);
            float acc = 0.f;
            int pidx = 0;
            if (doit) {
                int i = o < si ? o : si;
                int j = o < si ? si : o;
                pidx = i*(2*NN - i - 1)/2 + (j - i - 1);
                const float4* stp = (const float4*)(((o < si) ? svst : sust) + es*68);
                const float4* gop = (const float4*)(((o < si) ? g_u : g_v) +
                                    ((size_t)(b*NN + o)*LL + lbase + es)*HH);
                float c0=0,c1=0,c2=0,c3=0;
#pragma unroll
                for (int q = 0; q < 8; q++) {
                    int k4 = half*8 + q;
                    float4 gv = gop[k4];
                    float4 sv4 = stp[k4];
                    int k = k4*4;
                    c0 += fmaxf(gv.x + sv4.x + sbs1[k+0], 0.f)*sWs2[k+0];
                    c1 += fmaxf(gv.y + sv4.y + sbs1[k+1], 0.f)*sWs2[k+1];
                    c2 += fmaxf(gv.z + sv4.z + sbs1[k+2], 0.f)*sWs2[k+2];
                    c3 += fmaxf(gv.w + sv4.w + sbs1[k+3], 0.f)*sWs2[k+3];
                }
                acc = (c0+c1)+(c2+c3);
            }
            acc += __shfl_down_sync(0xffffffffu, acc, 1);
            acc += __shfl_down_sync(0xffffffffu, acc, 2);
            acc += __shfl_down_sync(0xffffffffu, acc, 4);
            acc += __shfl_down_sync(0xffffffffu, acc, 8);
            if (doit && (t & 15) == 0)
                g_part[((size_t)((s & 1)*BB + b)*PP + pidx)*32 + r] = acc;
        }

        // ===== anc output (reads sh2) =====
        if (t < 32) {
            int as = t >> 2, ch = t & 3;
            const float* h2 = sh2 + as*68;
            float a0=0,a1=0,a2=0,a3=0;
#pragma unroll
            for (int k = 0; k < 64; k += 4) {
                a0 += h2[k]   * sWd[k*4 + ch];
                a1 += h2[k+1] * sWd[(k+1)*4 + ch];
                a2 += h2[k+2] * sWd[(k+2)*4 + ch];
                a3 += h2[k+3] * sWd[(k+3)*4 + ch];
            }
            anc[(((size_t)b*NI + s)*LL + lbase + as)*4 + ch] = sbd[ch] + ((a0+a1)+(a2+a3));
        }
        // ===== pmpart (sum sh2 over sites) =====
        else if (t >= 64 && t < 128) {
            int hh = t - 64;
            float a0 = sh2[hh] + sh2[68 + hh];
            float a1 = sh2[136 + hh] + sh2[204 + hh];
            float a2 = sh2[272 + hh] + sh2[340 + hh];
            float a3 = sh2[408 + hh] + sh2[476 + hh];
            g_pmpart[((size_t)((s & 1)*BB + b)*BPB + r)*HH + hh] = ((a0+a1)+(a2+a3));
        }

        prev_si = si; prev_sj = sj;
        bbar(b, barid++);
    }

    // ---- epilogue ----
    if (r == 1 && t >= 256)
        do_branch(sm, b, NI - 1, (NI - 1) & 1, prev_si, prev_sj, bb2v, br, t - 256);
    if (r == 0 && t == 0) {
        g_loss[b] = s_loss;
        __threadfence();
        unsigned old = atomicAdd(&g_done, 1u);
        if (old == BB - 1) {
            g_done = 0;
            __threadfence();
            lo[0] = 0.25f * (__ldcg(&g_loss[0]) + __ldcg(&g_loss[1]) +
                             __ldcg(&g_loss[2]) + __ldcg(&g_loss[3]));
        }
    }
}

// ---------------- host ----------------
extern "C" void kernel_launch(void* const* d_in, const int* in_sizes, int n_in,
                              void* d_out, int out_size) {
    const float* leaf = (const float*)d_in[0];
    const int*   order = (const int*)d_in[1];
    const float* We  = (const float*)d_in[2];
    const float* be  = (const float*)d_in[3];
    const float* Wm1 = (const float*)d_in[4];
    const float* bm1 = (const float*)d_in[5];
    const float* Wm2 = (const float*)d_in[6];
    const float* bm2 = (const float*)d_in[7];
    const float* Ws1 = (const float*)d_in[8];
    const float* bs1 = (const float*)d_in[9];
    const float* Ws2 = (const float*)d_in[10];
    const float* bs2 = (const float*)d_in[11];
    const float* Wd  = (const float*)d_in[12];
    const float* bd  = (const float*)d_in[13];
    const float* Wb1 = (const float*)d_in[14];
    const float* bb1 = (const float*)d_in[15];
    const float* Wb2 = (const float*)d_in[16];
    const float* bb2 = (const float*)d_in[17];

    float* out = (float*)d_out;
    float* ml  = out;                              // [B, NI, P]
    float* anc = ml + (size_t)BB * NI * PP;        // [B, NI, L, 4]
    float* br  = anc + (size_t)BB * NI * LL * 4;   // [B, NI*2]
    float* lo  = br + (size_t)BB * NI * 2;         // scalar

    cudaFuncSetAttribute(phylo_persistent,
                         cudaFuncAttributeMaxDynamicSharedMemorySize, SMEM_BYTES);
    phylo_persistent<<<BB*BPB, NTHR, SMEM_BYTES>>>(
        leaf, order, We, be, Wm1, bm1, Wm2, bm2, Ws1, bs1, Ws2, bs2,
        Wd, bd, Wb1, bb1, Wb2, bb2, ml, anc, br, lo);
}